// round 12
// baseline (speedup 1.0000x reference)
#include <cuda_runtime.h>

typedef unsigned long long u64;

#define MAXN 100000
#define MAXE 1600000
#define D    128
#define SCAN_BS 512
#define MAX_SCAN_BLOCKS 256

// conv GEMM: 256 rows x 128 cols, 512 threads
#define GTC 256
#define ATS_C 260
#define AT_C_BYTES (128 * ATS_C * 4)       // 133120
#define WSTRIDE 140
#define W_BYTES (128 * WSTRIDE * 4)        // 71680
#define SMEM_C (AT_C_BYTES + W_BYTES)      // 204800

// heads GEMM: 128 rows x 2x128 cols, 512 threads
#define GTH 128
#define ATS_H 132
#define AT_H_BYTES (128 * ATS_H * 4)       // 67584
#define SMEM_H (AT_H_BYTES + 2 * W_BYTES)  // 210944

// ---------------- scratch (device globals; fully rewritten each launch) ----
__device__ __align__(16) float g_dis[MAXN];
__device__ __align__(16) float g_xw [(size_t)MAXN * D];
__device__ __align__(16) float g_h  [(size_t)MAXN * D];
__device__ int   g_cnt[MAXN];
__device__ int   g_incl[MAXN];
__device__ int   g_bsum[MAX_SCAN_BLOCKS];
__device__ int   g_rowstart[MAXN + 1];
__device__ int   g_cursor[MAXN];
__device__ __align__(16) int2 g_csr[MAXE];   // (src, coef-bits)
__device__ int g_is64;

// ---------------- edge dtype detection -------------------------------------
__global__ void k_detect(const int* __restrict__ e32, int nwords) {
    __shared__ int any;
    if (threadIdx.x == 0) any = 0;
    __syncthreads();
    int lim = nwords < 4096 ? nwords : 4096;
    for (int w = 1 + 2 * threadIdx.x; w < lim; w += 2 * blockDim.x)
        if (e32[w] != 0) any = 1;
    __syncthreads();
    if (threadIdx.x == 0) g_is64 = any ? 0 : 1;
}
__device__ __forceinline__ int edge_src(const int* e, int E, int i) {
    return g_is64 ? e[2 * (size_t)i] : e[i];
}
__device__ __forceinline__ int edge_dst(const int* e, int E, int i) {
    return g_is64 ? e[2 * ((size_t)E + i)] : e[(size_t)E + i];
}

// ---------------- zero (split so GEMM1 is the 4th launch for ncu) ----------
__global__ void k_zero_cnt(int n) {
    int i = blockIdx.x * blockDim.x + threadIdx.x;
    if (i < n) g_cnt[i] = 0;
}
__global__ void k_zero_cur(int n) {
    int i = blockIdx.x * blockDim.x + threadIdx.x;
    if (i < n) g_cursor[i] = 0;
}

// ---------------- CSR build -------------------------------------------------
__global__ void k_scan_block(int n) {
    __shared__ int sh[SCAN_BS];
    int i = blockIdx.x * SCAN_BS + threadIdx.x;
    int v = (i < n) ? g_cnt[i] : 0;
    if (i < n) g_dis[i] = rsqrtf((float)v + 1.0f);
    sh[threadIdx.x] = v;
    __syncthreads();
    #pragma unroll
    for (int off = 1; off < SCAN_BS; off <<= 1) {
        int t = (threadIdx.x >= off) ? sh[threadIdx.x - off] : 0;
        __syncthreads();
        sh[threadIdx.x] += t;
        __syncthreads();
    }
    if (i < n) g_incl[i] = sh[threadIdx.x];
    if (threadIdx.x == SCAN_BS - 1) g_bsum[blockIdx.x] = sh[threadIdx.x];
}
__global__ void k_scan_tops(int nblocks) {
    __shared__ int sh[MAX_SCAN_BLOCKS];
    int v = (threadIdx.x < nblocks) ? g_bsum[threadIdx.x] : 0;
    sh[threadIdx.x] = v;
    __syncthreads();
    #pragma unroll
    for (int off = 1; off < MAX_SCAN_BLOCKS; off <<= 1) {
        int t = (threadIdx.x >= off) ? sh[threadIdx.x - off] : 0;
        __syncthreads();
        sh[threadIdx.x] += t;
        __syncthreads();
    }
    g_bsum[threadIdx.x] = sh[threadIdx.x] - v;
}
__global__ void k_scan_add(int n, int E) {
    int i = blockIdx.x * SCAN_BS + threadIdx.x;
    if (i < n) {
        int excl = g_incl[i] - g_cnt[i] + g_bsum[blockIdx.x];
        g_rowstart[i] = excl;
        if (i == n - 1) g_rowstart[n] = excl + g_cnt[i];
    }
}
__global__ void k_fill(const int* __restrict__ edge, int E) {
    int i = blockIdx.x * blockDim.x + threadIdx.x;
    if (i < E) {
        int s = edge_src(edge, E, i);
        int d = edge_dst(edge, E, i);
        int pos = g_rowstart[d] + atomicAdd(&g_cursor[d], 1);
        g_csr[pos] = make_int2(s, __float_as_int(g_dis[s] * g_dis[d]));
    }
}

// ---------------- f32x2 helpers ---------------------------------------------
union F2U  { float2 f; u64 u; };
union F4U2 { float4 f; ulonglong2 u; };
__device__ __forceinline__ u64 dup_f32x2(float x) {
    F2U t; t.f = make_float2(x, x); return t.u;
}
__device__ __forceinline__ void ffma2(u64& acc, u64 a, u64 w) {
    asm("fma.rn.f32x2 %0, %1, %2, %0;" : "+l"(acc) : "l"(a), "l"(w));
}
__device__ __forceinline__ int wskew(int c) { return c + 4 * (c >> 5); }

// ---------------- GEMM core: warp = 16 rows (broadcast A), lane = 4 cols ----
// acc[rp][c] = f32x2 over row-pair (rbase+2rp, rbase+2rp+1), col cbase+c.
// Per k: 4 broadcast LDS.128 (A, natural row-pairs) + 1 LDS.128 (W)
//        + 4 dup MOVs + 32 FFMA2.
__device__ __forceinline__ void gemm_core(const float* __restrict__ At, int ats,
                                          const float* __restrict__ Ws,
                                          int rbase, int cb, u64 acc[8][4])
{
    #pragma unroll 4
    for (int k = 0; k < 128; k++) {
        int sw = ((k >> 2) & 7) << 2;
        const float* atk = At + k * ats;
        F4U2 a0, a1, a2, a3;
        a0.f = *(const float4*)(atk + ((rbase     ) ^ sw));
        a1.f = *(const float4*)(atk + ((rbase +  4) ^ sw));
        a2.f = *(const float4*)(atk + ((rbase +  8) ^ sw));
        a3.f = *(const float4*)(atk + ((rbase + 12) ^ sw));
        float4 wv = *(const float4*)(Ws + k * WSTRIDE + cb);
        u64 w0 = dup_f32x2(wv.x), w1 = dup_f32x2(wv.y);
        u64 w2 = dup_f32x2(wv.z), w3 = dup_f32x2(wv.w);
        ffma2(acc[0][0], a0.u.x, w0); ffma2(acc[0][1], a0.u.x, w1);
        ffma2(acc[0][2], a0.u.x, w2); ffma2(acc[0][3], a0.u.x, w3);
        ffma2(acc[1][0], a0.u.y, w0); ffma2(acc[1][1], a0.u.y, w1);
        ffma2(acc[1][2], a0.u.y, w2); ffma2(acc[1][3], a0.u.y, w3);
        ffma2(acc[2][0], a1.u.x, w0); ffma2(acc[2][1], a1.u.x, w1);
        ffma2(acc[2][2], a1.u.x, w2); ffma2(acc[2][3], a1.u.x, w3);
        ffma2(acc[3][0], a1.u.y, w0); ffma2(acc[3][1], a1.u.y, w1);
        ffma2(acc[3][2], a1.u.y, w2); ffma2(acc[3][3], a1.u.y, w3);
        ffma2(acc[4][0], a2.u.x, w0); ffma2(acc[4][1], a2.u.x, w1);
        ffma2(acc[4][2], a2.u.x, w2); ffma2(acc[4][3], a2.u.x, w3);
        ffma2(acc[5][0], a2.u.y, w0); ffma2(acc[5][1], a2.u.y, w1);
        ffma2(acc[5][2], a2.u.y, w2); ffma2(acc[5][3], a2.u.y, w3);
        ffma2(acc[6][0], a3.u.x, w0); ffma2(acc[6][1], a3.u.x, w1);
        ffma2(acc[6][2], a3.u.x, w2); ffma2(acc[6][3], a3.u.x, w3);
        ffma2(acc[7][0], a3.u.y, w0); ffma2(acc[7][1], a3.u.y, w1);
        ffma2(acc[7][2], a3.u.y, w2); ffma2(acc[7][3], a3.u.y, w3);
    }
}

// ---------------- conv GEMM: out = A @ W (no bias/relu) ---------------------
__global__ void __launch_bounds__(512, 1)
k_gemm_c(const float* __restrict__ A, int n,
         const float* __restrict__ W, float* __restrict__ out,
         const int* __restrict__ edge, int E, int hist)
{
    extern __shared__ __align__(16) char smem[];
    float* At = (float*)smem;                      // [128][ATS_C] swizzled
    float* Ws = (float*)(smem + AT_C_BYTES);       // [128][WSTRIDE] skewed

    const int tid = threadIdx.x;
    const int rowBlock = blockIdx.x * GTC;

    if (hist) {
        int per  = (E + gridDim.x - 1) / gridDim.x;
        int base = blockIdx.x * per;
        int lim  = base + per; if (lim > E) lim = E;
        for (int i = base + tid; i < lim; i += 512)
            atomicAdd(&g_cnt[edge_dst(edge, E, i)], 1);
    }

    // fill At: At[k][r ^ swz(k)] = A[r][k]
    #pragma unroll
    for (int i = 0; i < 16; i++) {
        int idx = tid + i * 512;           // 8192: r (0..255), c4 (0..31)
        int r   = idx >> 5;
        int c4  = idx & 31;
        int grow = rowBlock + r;
        float4 v = make_float4(0.f, 0.f, 0.f, 0.f);
        if (grow < n) v = ((const float4*)(A + (size_t)grow * D))[c4];
        int rs = r ^ ((c4 & 7) << 2);
        int k0 = 4 * c4;
        At[(k0 + 0) * ATS_C + rs] = v.x;
        At[(k0 + 1) * ATS_C + rs] = v.y;
        At[(k0 + 2) * ATS_C + rs] = v.z;
        At[(k0 + 3) * ATS_C + rs] = v.w;
    }
    // fill Ws skewed
    #pragma unroll
    for (int i = 0; i < 8; i++) {
        int idx = tid + i * 512;
        int k   = idx >> 5;
        int c4  = idx & 31;
        float4 v = ((const float4*)(W + (size_t)k * D))[c4];
        *(float4*)(Ws + k * WSTRIDE + wskew(4 * c4)) = v;
    }
    __syncthreads();

    const int wid  = tid >> 5, lane = tid & 31;
    const int rbase = wid * 16;
    const int cbase = lane * 4;
    const int cb    = wskew(cbase);

    u64 acc[8][4];
    #pragma unroll
    for (int rp = 0; rp < 8; rp++)
        #pragma unroll
        for (int c = 0; c < 4; c++) acc[rp][c] = 0ull;

    gemm_core(At, ATS_C, Ws, rbase, cb, acc);

    #pragma unroll
    for (int rp = 0; rp < 8; rp++) {
        int r0 = rowBlock + rbase + 2 * rp;
        F2U p0, p1, p2, p3;
        p0.u = acc[rp][0]; p1.u = acc[rp][1];
        p2.u = acc[rp][2]; p3.u = acc[rp][3];
        if (r0 < n)
            *(float4*)(out + (size_t)r0 * D + cbase) =
                make_float4(p0.f.x, p1.f.x, p2.f.x, p3.f.x);
        if (r0 + 1 < n)
            *(float4*)(out + (size_t)(r0 + 1) * D + cbase) =
                make_float4(p0.f.y, p1.f.y, p2.f.y, p3.f.y);
    }
}

// ---------------- heads GEMM: outv/outt = relu(A@Wv+bv / A@Wt+bt) -----------
// 128 rows; warps 0-7 -> head V, warps 8-15 -> head T (16 rows each).
__global__ void __launch_bounds__(512, 1)
k_gemm_h(const float* __restrict__ A, int n,
         const float* __restrict__ Wv, const float* __restrict__ bv,
         float* __restrict__ outv,
         const float* __restrict__ Wt, const float* __restrict__ bt,
         float* __restrict__ outt)
{
    extern __shared__ __align__(16) char smem[];
    float* At = (float*)smem;                        // [128][ATS_H]
    float* Ws = (float*)(smem + AT_H_BYTES);         // [2][128][WSTRIDE]

    const int tid = threadIdx.x;
    const int rowBlock = blockIdx.x * GTH;

    #pragma unroll
    for (int i = 0; i < 8; i++) {
        int idx = tid + i * 512;           // 4096: r (0..127), c4
        int r   = idx >> 5;
        int c4  = idx & 31;
        int grow = rowBlock + r;
        float4 v = make_float4(0.f, 0.f, 0.f, 0.f);
        if (grow < n) v = ((const float4*)(A + (size_t)grow * D))[c4];
        int rs = r ^ ((c4 & 7) << 2);
        int k0 = 4 * c4;
        At[(k0 + 0) * ATS_H + rs] = v.x;
        At[(k0 + 1) * ATS_H + rs] = v.y;
        At[(k0 + 2) * ATS_H + rs] = v.z;
        At[(k0 + 3) * ATS_H + rs] = v.w;
    }
    #pragma unroll
    for (int i = 0; i < 16; i++) {
        int idx = tid + i * 512;           // 8192: half, k, c4
        int half = idx >> 12;
        int j    = idx & 4095;
        int k    = j >> 5;
        int c4   = j & 31;
        const float* W = half ? Wt : Wv;
        float4 v = ((const float4*)(W + (size_t)k * D))[c4];
        *(float4*)(Ws + half * (W_BYTES / 4) + k * WSTRIDE + wskew(4 * c4)) = v;
    }
    __syncthreads();

    const int wid  = tid >> 5, lane = tid & 31;
    const int head = wid >> 3;
    const int rbase = (wid & 7) * 16;
    const int cbase = lane * 4;
    const int cb    = wskew(cbase);
    const float* Wsh = Ws + head * (W_BYTES / 4);

    u64 acc[8][4];
    #pragma unroll
    for (int rp = 0; rp < 8; rp++)
        #pragma unroll
        for (int c = 0; c < 4; c++) acc[rp][c] = 0ull;

    gemm_core(At, ATS_H, Wsh, rbase, cb, acc);

    const float* bias = head ? bt : bv;
    float*       out  = head ? outt : outv;
    float4 b = *(const float4*)(bias + cbase);
    #pragma unroll
    for (int rp = 0; rp < 8; rp++) {
        int r0 = rowBlock + rbase + 2 * rp;
        F2U p0, p1, p2, p3;
        p0.u = acc[rp][0]; p1.u = acc[rp][1];
        p2.u = acc[rp][2]; p3.u = acc[rp][3];
        if (r0 < n) {
            float4 o = make_float4(fmaxf(p0.f.x + b.x, 0.f),
                                   fmaxf(p1.f.x + b.y, 0.f),
                                   fmaxf(p2.f.x + b.z, 0.f),
                                   fmaxf(p3.f.x + b.w, 0.f));
            *(float4*)(out + (size_t)r0 * D + cbase) = o;
        }
        if (r0 + 1 < n) {
            float4 o = make_float4(fmaxf(p0.f.y + b.x, 0.f),
                                   fmaxf(p1.f.y + b.y, 0.f),
                                   fmaxf(p2.f.y + b.z, 0.f),
                                   fmaxf(p3.f.y + b.w, 0.f));
            *(float4*)(out + (size_t)(r0 + 1) * D + cbase) = o;
        }
    }
}

// ---------------- CSR gather aggregation -----------------------------------
__global__ void k_gather(const float* __restrict__ xw,
                         float* __restrict__ out,
                         const float* __restrict__ bias, int relu,
                         int n)
{
    int warp = (blockIdx.x * blockDim.x + threadIdx.x) >> 5;
    int lane = threadIdx.x & 31;
    if (warp >= n) return;
    const int d = warp;

    float dis = g_dis[d];
    float dis2 = dis * dis;
    float4 self = ((const float4*)(xw + (size_t)d * D))[lane];
    float4 acc;
    acc.x = self.x * dis2; acc.y = self.y * dis2;
    acc.z = self.z * dis2; acc.w = self.w * dis2;

    int e   = g_rowstart[d];
    int end = g_rowstart[d + 1];

    for (; e + 1 < end; e += 2) {
        int2 e0 = g_csr[e];
        int2 e1 = g_csr[e + 1];
        float c0 = __int_as_float(e0.y);
        float c1 = __int_as_float(e1.y);
        float4 v0 = ((const float4*)(xw + (size_t)e0.x * D))[lane];
        float4 v1 = ((const float4*)(xw + (size_t)e1.x * D))[lane];
        acc.x = fmaf(c0, v0.x, acc.x); acc.y = fmaf(c0, v0.y, acc.y);
        acc.z = fmaf(c0, v0.z, acc.z); acc.w = fmaf(c0, v0.w, acc.w);
        acc.x = fmaf(c1, v1.x, acc.x); acc.y = fmaf(c1, v1.y, acc.y);
        acc.z = fmaf(c1, v1.z, acc.z); acc.w = fmaf(c1, v1.w, acc.w);
    }
    if (e < end) {
        int2 e0 = g_csr[e];
        float c0 = __int_as_float(e0.y);
        float4 v0 = ((const float4*)(xw + (size_t)e0.x * D))[lane];
        acc.x = fmaf(c0, v0.x, acc.x); acc.y = fmaf(c0, v0.y, acc.y);
        acc.z = fmaf(c0, v0.z, acc.z); acc.w = fmaf(c0, v0.w, acc.w);
    }

    const int col = lane * 4;
    acc.x += bias[col]; acc.y += bias[col + 1];
    acc.z += bias[col + 2]; acc.w += bias[col + 3];
    if (relu) {
        acc.x = fmaxf(acc.x, 0.f); acc.y = fmaxf(acc.y, 0.f);
        acc.z = fmaxf(acc.z, 0.f); acc.w = fmaxf(acc.w, 0.f);
    }
    ((float4*)(out + (size_t)d * D))[lane] = acc;
}

// ---------------- launch ---------------------------------------------------
extern "C" void kernel_launch(void* const* d_in, const int* in_sizes, int n_in,
                              void* d_out, int out_size)
{
    const float* x    = (const float*)d_in[0];
    const int*   edge = (const int*)d_in[1];   // int32 or int64 (detected)
    const float* W1 = (const float*)d_in[2]; const float* b1 = (const float*)d_in[3];
    const float* W2 = (const float*)d_in[4]; const float* b2 = (const float*)d_in[5];
    const float* Wv = (const float*)d_in[6]; const float* bv = (const float*)d_in[7];
    const float* Wt = (const float*)d_in[8]; const float* bt = (const float*)d_in[9];

    const int n = in_sizes[0] / D;
    const int E = in_sizes[1] / 2;

    float* out_h = (float*)d_out;
    float* out_v = out_h + (size_t)n * D;
    float* out_t = out_v + (size_t)n * D;

    float* xw = nullptr; cudaGetSymbolAddress((void**)&xw, g_xw);
    float* h  = nullptr; cudaGetSymbolAddress((void**)&h,  g_h);

    cudaFuncSetAttribute(k_gemm_c, cudaFuncAttributeMaxDynamicSharedMemorySize, SMEM_C);
    cudaFuncSetAttribute(k_gemm_h, cudaFuncAttributeMaxDynamicSharedMemorySize, SMEM_H);

    const int TB = 256;
    const int nscan = (n + SCAN_BS - 1) / SCAN_BS;
    const int convGrid   = (n + GTC - 1) / GTC;
    const int headGrid   = (n + GTH - 1) / GTH;
    const int gatherGrid = (n + 7) / 8;

    // launches 1-3 small so the conv1 GEMM is the 4th (ncu sample slot)
    k_detect<<<1, 512>>>(edge, 2 * E);
    k_zero_cnt<<<(n + TB - 1) / TB, TB>>>(n);
    k_zero_cur<<<(n + TB - 1) / TB, TB>>>(n);
    // 4: conv1 GEMM (+ folded degree histogram)
    k_gemm_c<<<convGrid, 512, SMEM_C>>>(x, n, W1, xw, edge, E, 1);
    // normalization + CSR
    k_scan_block<<<nscan, SCAN_BS>>>(n);
    k_scan_tops<<<1, MAX_SCAN_BLOCKS>>>(nscan);
    k_scan_add<<<nscan, SCAN_BS>>>(n, E);
    k_fill<<<(E + TB - 1) / TB, TB>>>(edge, E);
    // conv1 aggregate -> h
    k_gather<<<gatherGrid, TB>>>(xw, h, b1, 1, n);
    // conv2
    k_gemm_c<<<convGrid, 512, SMEM_C>>>(h, n, W2, xw, nullptr, 0, 0);
    k_gather<<<gatherGrid, TB>>>(xw, out_h, b2, 0, n);
    // heads: one launch, both W
    k_gemm_h<<<headGrid, 512, SMEM_H>>>(out_h, n, Wv, bv, out_v, Wt, bt, out_t);
}

// round 13
// speedup vs baseline: 1.0571x; 1.0571x over previous
#include <cuda_runtime.h>

typedef unsigned long long u64;

#define MAXN 100000
#define MAXE 1600000
#define D    128
#define SCAN_BS 512
#define MAX_SCAN_BLOCKS 256

#define GT 64                              // GEMM rows per CTA
#define ATS 68                             // At stride (floats)
#define AT_BYTES (128 * ATS * 4)           // 34816
#define WSTRIDE 140                        // skewed W stride (floats)
#define W_BYTES (128 * WSTRIDE * 4)        // 71680
#define GEMM_SMEM (AT_BYTES + W_BYTES)     // 106496 -> 2 CTAs/SM

// ---------------- scratch (device globals; fully rewritten each launch) ----
__device__ __align__(16) float g_dis[MAXN];
__device__ __align__(16) float g_xw [(size_t)MAXN * D];
__device__ __align__(16) float g_h  [(size_t)MAXN * D];
__device__ int   g_cnt[MAXN];
__device__ int   g_incl[MAXN];
__device__ int   g_bsum[MAX_SCAN_BLOCKS];
__device__ int   g_rowstart[MAXN + 1];
__device__ int   g_cursor[MAXN];
__device__ __align__(16) int2 g_csr[MAXE];   // (src, coef-bits)
__device__ int g_is64;

// ---------------- edge dtype detection -------------------------------------
__global__ void k_detect(const int* __restrict__ e32, int nwords) {
    __shared__ int any;
    if (threadIdx.x == 0) any = 0;
    __syncthreads();
    int lim = nwords < 4096 ? nwords : 4096;
    for (int w = 1 + 2 * threadIdx.x; w < lim; w += 2 * blockDim.x)
        if (e32[w] != 0) any = 1;
    __syncthreads();
    if (threadIdx.x == 0) g_is64 = any ? 0 : 1;
}
__device__ __forceinline__ int edge_src(const int* e, int E, int i) {
    return g_is64 ? e[2 * (size_t)i] : e[i];
}
__device__ __forceinline__ int edge_dst(const int* e, int E, int i) {
    return g_is64 ? e[2 * ((size_t)E + i)] : e[(size_t)E + i];
}

// ---------------- zero (split so GEMM1 is the 4th launch for ncu) ----------
__global__ void k_zero_cnt(int n) {
    int i = blockIdx.x * blockDim.x + threadIdx.x;
    if (i < n) g_cnt[i] = 0;
}
__global__ void k_zero_cur(int n) {
    int i = blockIdx.x * blockDim.x + threadIdx.x;
    if (i < n) g_cursor[i] = 0;
}

// ---------------- CSR build -------------------------------------------------
__global__ void k_scan_block(int n) {
    __shared__ int sh[SCAN_BS];
    int i = blockIdx.x * SCAN_BS + threadIdx.x;
    int v = (i < n) ? g_cnt[i] : 0;
    if (i < n) g_dis[i] = rsqrtf((float)v + 1.0f);
    sh[threadIdx.x] = v;
    __syncthreads();
    #pragma unroll
    for (int off = 1; off < SCAN_BS; off <<= 1) {
        int t = (threadIdx.x >= off) ? sh[threadIdx.x - off] : 0;
        __syncthreads();
        sh[threadIdx.x] += t;
        __syncthreads();
    }
    if (i < n) g_incl[i] = sh[threadIdx.x];
    if (threadIdx.x == SCAN_BS - 1) g_bsum[blockIdx.x] = sh[threadIdx.x];
}
__global__ void k_scan_tops(int nblocks) {
    __shared__ int sh[MAX_SCAN_BLOCKS];
    int v = (threadIdx.x < nblocks) ? g_bsum[threadIdx.x] : 0;
    sh[threadIdx.x] = v;
    __syncthreads();
    #pragma unroll
    for (int off = 1; off < MAX_SCAN_BLOCKS; off <<= 1) {
        int t = (threadIdx.x >= off) ? sh[threadIdx.x - off] : 0;
        __syncthreads();
        sh[threadIdx.x] += t;
        __syncthreads();
    }
    g_bsum[threadIdx.x] = sh[threadIdx.x] - v;
}
__global__ void k_scan_add(int n, int E) {
    int i = blockIdx.x * SCAN_BS + threadIdx.x;
    if (i < n) {
        int excl = g_incl[i] - g_cnt[i] + g_bsum[blockIdx.x];
        g_rowstart[i] = excl;
        if (i == n - 1) g_rowstart[n] = excl + g_cnt[i];
    }
}
__global__ void k_fill(const int* __restrict__ edge, int E) {
    int i = blockIdx.x * blockDim.x + threadIdx.x;
    if (i < E) {
        int s = edge_src(edge, E, i);
        int d = edge_dst(edge, E, i);
        int pos = g_rowstart[d] + atomicAdd(&g_cursor[d], 1);
        g_csr[pos] = make_int2(s, __float_as_int(g_dis[s] * g_dis[d]));
    }
}

// ---------------- f32x2 helpers ---------------------------------------------
union F2U  { float2 f; u64 u; };
union F4U2 { float4 f; ulonglong2 u; };
__device__ __forceinline__ u64 dup_f32x2(float x) {
    F2U t; t.f = make_float2(x, x); return t.u;
}
__device__ __forceinline__ void ffma2(u64& acc, u64 a, u64 w) {
    asm("fma.rn.f32x2 %0, %1, %2, %0;" : "+l"(acc) : "l"(a), "l"(w));
}
__device__ __forceinline__ int wskew(int c) { return c + 4 * (c >> 5); }

// ---------------- GEMM: out = f(A @ W + bias) -------------------------------
// 64 rows x 128 cols x K=128, 256 threads, 2 CTAs/SM (106.5KB smem).
// Warp w: rows w*8..w*8+7 (broadcast A); lane: cols lane*4..+3.
// Thread: 8 rows (4 row-pairs) x 4 cols. Per k:
//   2 broadcast LDS.128 (A row-pairs, natural u64 halves; XOR-swizzled tile)
//   + 1 LDS.128 (W, skewed) + 4 W-dup MOVs + 16 FFMA2 (32 MACs).
__global__ void __launch_bounds__(256, 2)
k_gemm(const float* __restrict__ A, int n,
       const float* __restrict__ W, const float* __restrict__ bias,
       int relu, float* __restrict__ out,
       const int* __restrict__ edge, int E, int hist)
{
    extern __shared__ __align__(16) char smem[];
    float* At = (float*)smem;                  // [128][ATS] swizzled transpose
    float* Ws = (float*)(smem + AT_BYTES);     // [128][WSTRIDE] skewed

    const int tid = threadIdx.x;
    const int rowBlock = blockIdx.x * GT;

    // folded degree histogram (fire-and-forget REDs)
    if (hist) {
        int per  = (E + gridDim.x - 1) / gridDim.x;
        int base = blockIdx.x * per;
        int lim  = base + per; if (lim > E) lim = E;
        for (int i = base + tid; i < lim; i += 256)
            atomicAdd(&g_cnt[edge_dst(edge, E, i)], 1);
    }

    // fill At: At[k][r ^ ((k>>2)&7)<<2] = A[r][k]   (64 rows x 32 float4)
    #pragma unroll
    for (int i = 0; i < 8; i++) {
        int idx = tid + i * 256;           // 0..2047: r (0..63), c4 (0..31)
        int r   = idx >> 5;
        int c4  = idx & 31;
        int grow = rowBlock + r;
        float4 v = make_float4(0.f, 0.f, 0.f, 0.f);
        if (grow < n) v = ((const float4*)(A + (size_t)grow * D))[c4];
        int rs = r ^ ((c4 & 7) << 2);
        int k0 = 4 * c4;
        At[(k0 + 0) * ATS + rs] = v.x;
        At[(k0 + 1) * ATS + rs] = v.y;
        At[(k0 + 2) * ATS + rs] = v.z;
        At[(k0 + 3) * ATS + rs] = v.w;
    }
    // fill Ws skewed: Ws[k][wskew(c)] = W[k][c]
    #pragma unroll
    for (int i = 0; i < 16; i++) {
        int idx = tid + i * 256;           // 4096 float4s: k, c4
        int k   = idx >> 5;
        int c4  = idx & 31;
        float4 v = ((const float4*)(W + (size_t)k * D))[c4];
        *(float4*)(Ws + k * WSTRIDE + wskew(4 * c4)) = v;
    }
    __syncthreads();

    const int wid  = tid >> 5, lane = tid & 31;
    const int rbase = wid * 8;
    const int cbase = lane * 4;
    const int cb    = wskew(cbase);

    u64 acc[4][4];                          // [row-pair][col]
    #pragma unroll
    for (int rp = 0; rp < 4; rp++)
        #pragma unroll
        for (int c = 0; c < 4; c++) acc[rp][c] = 0ull;

    #pragma unroll 4
    for (int k = 0; k < 128; k++) {
        int sw = ((k >> 2) & 7) << 2;
        const float* atk = At + k * ATS;
        F4U2 a01, a23;
        a01.f = *(const float4*)(atk + ((rbase    ) ^ sw));  // rows r..r+3
        a23.f = *(const float4*)(atk + ((rbase + 4) ^ sw));  // rows r+4..r+7
        float4 wv = *(const float4*)(Ws + k * WSTRIDE + cb);
        u64 w0 = dup_f32x2(wv.x), w1 = dup_f32x2(wv.y);
        u64 w2 = dup_f32x2(wv.z), w3 = dup_f32x2(wv.w);
        ffma2(acc[0][0], a01.u.x, w0); ffma2(acc[0][1], a01.u.x, w1);
        ffma2(acc[0][2], a01.u.x, w2); ffma2(acc[0][3], a01.u.x, w3);
        ffma2(acc[1][0], a01.u.y, w0); ffma2(acc[1][1], a01.u.y, w1);
        ffma2(acc[1][2], a01.u.y, w2); ffma2(acc[1][3], a01.u.y, w3);
        ffma2(acc[2][0], a23.u.x, w0); ffma2(acc[2][1], a23.u.x, w1);
        ffma2(acc[2][2], a23.u.x, w2); ffma2(acc[2][3], a23.u.x, w3);
        ffma2(acc[3][0], a23.u.y, w0); ffma2(acc[3][1], a23.u.y, w1);
        ffma2(acc[3][2], a23.u.y, w2); ffma2(acc[3][3], a23.u.y, w3);
    }

    // epilogue
    float4 b = make_float4(0.f, 0.f, 0.f, 0.f);
    if (bias) b = *(const float4*)(bias + cbase);
    #pragma unroll
    for (int rp = 0; rp < 4; rp++) {
        int r0 = rowBlock + rbase + 2 * rp;
        F2U p0, p1, p2, p3;
        p0.u = acc[rp][0]; p1.u = acc[rp][1];
        p2.u = acc[rp][2]; p3.u = acc[rp][3];
        if (r0 < n) {
            float4 o = make_float4(p0.f.x + b.x, p1.f.x + b.y,
                                   p2.f.x + b.z, p3.f.x + b.w);
            if (relu) {
                o.x = fmaxf(o.x, 0.f); o.y = fmaxf(o.y, 0.f);
                o.z = fmaxf(o.z, 0.f); o.w = fmaxf(o.w, 0.f);
            }
            *(float4*)(out + (size_t)r0 * D + cbase) = o;
        }
        if (r0 + 1 < n) {
            float4 o = make_float4(p0.f.y + b.x, p1.f.y + b.y,
                                   p2.f.y + b.z, p3.f.y + b.w);
            if (relu) {
                o.x = fmaxf(o.x, 0.f); o.y = fmaxf(o.y, 0.f);
                o.z = fmaxf(o.z, 0.f); o.w = fmaxf(o.w, 0.f);
            }
            *(float4*)(out + (size_t)(r0 + 1) * D + cbase) = o;
        }
    }
}

// ---------------- CSR gather aggregation -----------------------------------
__global__ void k_gather(const float* __restrict__ xw,
                         float* __restrict__ out,
                         const float* __restrict__ bias, int relu,
                         int n)
{
    int warp = (blockIdx.x * blockDim.x + threadIdx.x) >> 5;
    int lane = threadIdx.x & 31;
    if (warp >= n) return;
    const int d = warp;

    float dis = g_dis[d];
    float dis2 = dis * dis;
    float4 self = ((const float4*)(xw + (size_t)d * D))[lane];
    float4 acc;
    acc.x = self.x * dis2; acc.y = self.y * dis2;
    acc.z = self.z * dis2; acc.w = self.w * dis2;

    int e   = g_rowstart[d];
    int end = g_rowstart[d + 1];

    for (; e + 1 < end; e += 2) {
        int2 e0 = g_csr[e];
        int2 e1 = g_csr[e + 1];
        float c0 = __int_as_float(e0.y);
        float c1 = __int_as_float(e1.y);
        float4 v0 = ((const float4*)(xw + (size_t)e0.x * D))[lane];
        float4 v1 = ((const float4*)(xw + (size_t)e1.x * D))[lane];
        acc.x = fmaf(c0, v0.x, acc.x); acc.y = fmaf(c0, v0.y, acc.y);
        acc.z = fmaf(c0, v0.z, acc.z); acc.w = fmaf(c0, v0.w, acc.w);
        acc.x = fmaf(c1, v1.x, acc.x); acc.y = fmaf(c1, v1.y, acc.y);
        acc.z = fmaf(c1, v1.z, acc.z); acc.w = fmaf(c1, v1.w, acc.w);
    }
    if (e < end) {
        int2 e0 = g_csr[e];
        float c0 = __int_as_float(e0.y);
        float4 v0 = ((const float4*)(xw + (size_t)e0.x * D))[lane];
        acc.x = fmaf(c0, v0.x, acc.x); acc.y = fmaf(c0, v0.y, acc.y);
        acc.z = fmaf(c0, v0.z, acc.z); acc.w = fmaf(c0, v0.w, acc.w);
    }

    const int col = lane * 4;
    acc.x += bias[col]; acc.y += bias[col + 1];
    acc.z += bias[col + 2]; acc.w += bias[col + 3];
    if (relu) {
        acc.x = fmaxf(acc.x, 0.f); acc.y = fmaxf(acc.y, 0.f);
        acc.z = fmaxf(acc.z, 0.f); acc.w = fmaxf(acc.w, 0.f);
    }
    ((float4*)(out + (size_t)d * D))[lane] = acc;
}

// ---------------- launch ---------------------------------------------------
extern "C" void kernel_launch(void* const* d_in, const int* in_sizes, int n_in,
                              void* d_out, int out_size)
{
    const float* x    = (const float*)d_in[0];
    const int*   edge = (const int*)d_in[1];   // int32 or int64 (detected)
    const float* W1 = (const float*)d_in[2]; const float* b1 = (const float*)d_in[3];
    const float* W2 = (const float*)d_in[4]; const float* b2 = (const float*)d_in[5];
    const float* Wv = (const float*)d_in[6]; const float* bv = (const float*)d_in[7];
    const float* Wt = (const float*)d_in[8]; const float* bt = (const float*)d_in[9];

    const int n = in_sizes[0] / D;
    const int E = in_sizes[1] / 2;

    float* out_h = (float*)d_out;
    float* out_v = out_h + (size_t)n * D;
    float* out_t = out_v + (size_t)n * D;

    float* xw = nullptr; cudaGetSymbolAddress((void**)&xw, g_xw);
    float* h  = nullptr; cudaGetSymbolAddress((void**)&h,  g_h);

    cudaFuncSetAttribute(k_gemm, cudaFuncAttributeMaxDynamicSharedMemorySize, GEMM_SMEM);

    const int TB = 256;
    const int nscan = (n + SCAN_BS - 1) / SCAN_BS;
    const int gemmGrid   = (n + GT - 1) / GT;
    const int gatherGrid = (n + 7) / 8;

    // launches 1-3 small so the conv1 GEMM is the 4th (ncu sample slot)
    k_detect<<<1, 512>>>(edge, 2 * E);
    k_zero_cnt<<<(n + TB - 1) / TB, TB>>>(n);
    k_zero_cur<<<(n + TB - 1) / TB, TB>>>(n);
    // 4: conv1 GEMM (+ folded degree histogram)
    k_gemm<<<gemmGrid, TB, GEMM_SMEM>>>(x, n, W1, nullptr, 0, xw, edge, E, 1);
    // normalization + CSR
    k_scan_block<<<nscan, SCAN_BS>>>(n);
    k_scan_tops<<<1, MAX_SCAN_BLOCKS>>>(nscan);
    k_scan_add<<<nscan, SCAN_BS>>>(n, E);
    k_fill<<<(E + TB - 1) / TB, TB>>>(edge, E);
    // conv1 aggregate -> h
    k_gather<<<gatherGrid, TB>>>(xw, h, b1, 1, n);
    // conv2
    k_gemm<<<gemmGrid, TB, GEMM_SMEM>>>(h, n, W2, nullptr, 0, xw,
                                        nullptr, 0, 0);
    k_gather<<<gatherGrid, TB>>>(xw, out_h, b2, 0, n);
    // heads
    k_gemm<<<gemmGrid, TB, GEMM_SMEM>>>(out_h, n, Wv, bv, 1, out_v,
                                        nullptr, 0, 0);
    k_gemm<<<gemmGrid, TB, GEMM_SMEM>>>(out_h, n, Wt, bt, 1, out_t,
                                        nullptr, 0, 0);
}

// round 14
// speedup vs baseline: 1.4131x; 1.3368x over previous
#include <cuda_runtime.h>
#include <cuda_bf16.h>

typedef unsigned long long u64;
typedef unsigned int u32;

#define MAXN 100000
#define MAXE 1600000
#define D    128
#define SCAN_BS 512
#define MAX_SCAN_BLOCKS 256

#define GT  64                     // GEMM rows per CTA
#define AST 136                    // A smem stride (bf16 elems)
#define WST 136                    // W smem stride (bf16 elems)
#define AL_OFF (64 * AST)          // elem offsets inside smem
#define WH_OFF (2 * 64 * AST)
#define WL_OFF (2 * 64 * AST + 128 * WST)
#define SMEM_TC ((2 * 64 * AST + 2 * 128 * WST) * 2)   // 104448 B -> 2 CTAs/SM
#define WIMG_ELEMS (128 * WST)

// ---------------- scratch (device globals; fully rewritten each launch) ----
__device__ __align__(16) float g_dis[MAXN];
__device__ __align__(16) float g_xw [(size_t)MAXN * D];
__device__ __align__(16) float g_h  [(size_t)MAXN * D];
__device__ int   g_cnt[MAXN];
__device__ int   g_incl[MAXN];
__device__ int   g_bsum[MAX_SCAN_BLOCKS];
__device__ int   g_rowstart[MAXN + 1];
__device__ int   g_cursor[MAXN];
__device__ __align__(16) int2 g_csr[MAXE];   // (src, coef-bits)
__device__ int g_is64;
// pre-transposed bf16 hi/lo images of W1,W2,Wv,Wt (pairs: 2i=hi, 2i+1=lo)
__device__ __align__(16) __nv_bfloat16 g_wimg[8][WIMG_ELEMS];

// ---------------- edge dtype detection -------------------------------------
__global__ void k_detect(const int* __restrict__ e32, int nwords) {
    __shared__ int any;
    if (threadIdx.x == 0) any = 0;
    __syncthreads();
    int lim = nwords < 4096 ? nwords : 4096;
    for (int w = 1 + 2 * threadIdx.x; w < lim; w += 2 * blockDim.x)
        if (e32[w] != 0) any = 1;
    __syncthreads();
    if (threadIdx.x == 0) g_is64 = any ? 0 : 1;
}
__device__ __forceinline__ int edge_src(const int* e, int E, int i) {
    return g_is64 ? e[2 * (size_t)i] : e[i];
}
__device__ __forceinline__ int edge_dst(const int* e, int E, int i) {
    return g_is64 ? e[2 * ((size_t)E + i)] : e[(size_t)E + i];
}

// ---------------- zero ------------------------------------------------------
__global__ void k_zero(int n) {
    int i = blockIdx.x * blockDim.x + threadIdx.x;
    if (i < n) { g_cnt[i] = 0; g_cursor[i] = 0; }
}

// ---------------- CSR build -------------------------------------------------
__global__ void k_scan_block(int n) {
    __shared__ int sh[SCAN_BS];
    int i = blockIdx.x * SCAN_BS + threadIdx.x;
    int v = (i < n) ? g_cnt[i] : 0;
    if (i < n) g_dis[i] = rsqrtf((float)v + 1.0f);
    sh[threadIdx.x] = v;
    __syncthreads();
    #pragma unroll
    for (int off = 1; off < SCAN_BS; off <<= 1) {
        int t = (threadIdx.x >= off) ? sh[threadIdx.x - off] : 0;
        __syncthreads();
        sh[threadIdx.x] += t;
        __syncthreads();
    }
    if (i < n) g_incl[i] = sh[threadIdx.x];
    if (threadIdx.x == SCAN_BS - 1) g_bsum[blockIdx.x] = sh[threadIdx.x];
}
__global__ void k_scan_tops(int nblocks) {
    __shared__ int sh[MAX_SCAN_BLOCKS];
    int v = (threadIdx.x < nblocks) ? g_bsum[threadIdx.x] : 0;
    sh[threadIdx.x] = v;
    __syncthreads();
    #pragma unroll
    for (int off = 1; off < MAX_SCAN_BLOCKS; off <<= 1) {
        int t = (threadIdx.x >= off) ? sh[threadIdx.x - off] : 0;
        __syncthreads();
        sh[threadIdx.x] += t;
        __syncthreads();
    }
    g_bsum[threadIdx.x] = sh[threadIdx.x] - v;
}
__global__ void k_scan_add(int n, int E) {
    int i = blockIdx.x * SCAN_BS + threadIdx.x;
    if (i < n) {
        int excl = g_incl[i] - g_cnt[i] + g_bsum[blockIdx.x];
        g_rowstart[i] = excl;
        if (i == n - 1) g_rowstart[n] = excl + g_cnt[i];
    }
}
__global__ void k_fill(const int* __restrict__ edge, int E) {
    int i = blockIdx.x * blockDim.x + threadIdx.x;
    if (i < E) {
        int s = edge_src(edge, E, i);
        int d = edge_dst(edge, E, i);
        int pos = g_rowstart[d] + atomicAdd(&g_cursor[d], 1);
        g_csr[pos] = make_int2(s, __float_as_int(g_dis[s] * g_dis[d]));
    }
}

// ---------------- bf16 helpers ----------------------------------------------
__device__ __forceinline__ u32 pack_bf2(float x, float y) {
    u32 lo = (u32)__bfloat16_as_ushort(__float2bfloat16_rn(x));
    u32 hi = (u32)__bfloat16_as_ushort(__float2bfloat16_rn(y));
    return lo | (hi << 16);
}
__device__ __forceinline__ void mma16816(float* c, const u32* a, const u32* b) {
    asm volatile(
        "mma.sync.aligned.m16n8k16.row.col.f32.bf16.bf16.f32 "
        "{%0,%1,%2,%3},{%4,%5,%6,%7},{%8,%9},{%0,%1,%2,%3};"
        : "+f"(c[0]), "+f"(c[1]), "+f"(c[2]), "+f"(c[3])
        : "r"(a[0]), "r"(a[1]), "r"(a[2]), "r"(a[3]), "r"(b[0]), "r"(b[1]));
}

// ---------------- W prep: fp32 row-major -> transposed bf16 hi/lo images ----
// img_h/l[n*WST + k] = hi/lo of W[k][n]  (exact smem image for float4 copy)
__global__ void k_wprep(const float* __restrict__ Wa, const float* __restrict__ Wb,
                        const float* __restrict__ Wc, const float* __restrict__ Wd)
{
    const float* Ws4[4] = {Wa, Wb, Wc, Wd};
    const float* W = Ws4[blockIdx.x];
    __nv_bfloat16* imgh = g_wimg[2 * blockIdx.x];
    __nv_bfloat16* imgl = g_wimg[2 * blockIdx.x + 1];
    int tid = threadIdx.x;
    #pragma unroll
    for (int i = 0; i < 16; i++) {
        int idx = tid + i * 256;       // 4096 float4s: k = idx>>5, n0 = 4*(idx&31)
        int k   = idx >> 5;
        int n0  = (idx & 31) * 4;
        float4 w = ((const float4*)(W + (size_t)k * D))[idx & 31];
        float ws[4] = {w.x, w.y, w.z, w.w};
        #pragma unroll
        for (int j = 0; j < 4; j++) {
            float hi = __bfloat162float(__float2bfloat16_rn(ws[j]));
            imgh[(n0 + j) * WST + k] = __float2bfloat16_rn(hi);
            imgl[(n0 + j) * WST + k] = __float2bfloat16_rn(ws[j] - hi);
        }
    }
}

// ---------------- tensor-core GEMM (bf16 3-term split, fp32-grade) ----------
// out = f(A @ W + bias).  64 rows x 128 cols x K=128, 256 threads,
// 2 CTAs/SM (104.4KB smem). Warp (wm=wid>>2, wn=wid&3) tile 32x32:
// 2x4 m16n8k16 frags, 3 terms (AhBh + AlBh + AhBl).
__global__ void __launch_bounds__(256, 2)
k_gemm_tc(const float* __restrict__ A, int n, int wsel,
          const float* __restrict__ bias, int relu, float* __restrict__ out,
          const int* __restrict__ edge, int E, int hist)
{
    extern __shared__ __align__(16) __nv_bfloat16 sm[];
    __nv_bfloat16* Ah = sm;
    __nv_bfloat16* Al = sm + AL_OFF;
    __nv_bfloat16* Wh = sm + WH_OFF;
    __nv_bfloat16* Wl = sm + WL_OFF;

    const int tid = threadIdx.x;
    const int rowBlock = blockIdx.x * GT;

    // folded degree histogram (fire-and-forget REDs under tensor-bound)
    if (hist) {
        int per  = (E + gridDim.x - 1) / gridDim.x;
        int base = blockIdx.x * per;
        int lim  = base + per; if (lim > E) lim = E;
        for (int i = base + tid; i < lim; i += 256)
            atomicAdd(&g_cnt[edge_dst(edge, E, i)], 1);
    }

    // ---- fill A hi/lo (row-major, stride AST), zero OOB rows ---------------
    #pragma unroll
    for (int i = 0; i < 8; i++) {
        int idx = tid + i * 256;       // 2048: r = idx>>5 (0..63), c4 = idx&31
        int r   = idx >> 5;
        int c4  = idx & 31;
        int grow = rowBlock + r;
        float4 v = make_float4(0.f, 0.f, 0.f, 0.f);
        if (grow < n) v = ((const float4*)(A + (size_t)grow * D))[c4];
        float hx = __bfloat162float(__float2bfloat16_rn(v.x));
        float hy = __bfloat162float(__float2bfloat16_rn(v.y));
        float hz = __bfloat162float(__float2bfloat16_rn(v.z));
        float hw = __bfloat162float(__float2bfloat16_rn(v.w));
        u32* ph = (u32*)(Ah + r * AST + c4 * 4);
        u32* pl = (u32*)(Al + r * AST + c4 * 4);
        ph[0] = pack_bf2(hx, hy);             ph[1] = pack_bf2(hz, hw);
        pl[0] = pack_bf2(v.x - hx, v.y - hy); pl[1] = pack_bf2(v.z - hz, v.w - hw);
    }
    // ---- copy W hi/lo images (verbatim; images adjacent, smem contiguous) --
    {
        const float4* src = (const float4*)g_wimg[2 * wsel];
        float4* dst = (float4*)Wh;            // Wh then Wl contiguous
        #pragma unroll
        for (int i = 0; i < 17; i++)          // 2*34816B / 16 = 4352 float4s
            dst[tid + i * 256] = src[tid + i * 256];
    }
    __syncthreads();

    const int wid  = tid >> 5, lane = tid & 31;
    const int wm = wid >> 2;        // 0..1 -> rows wm*32
    const int wn = wid & 3;         // 0..3 -> cols wn*32
    const int g  = lane >> 2, t = lane & 3;

    float acc[2][4][4];
    #pragma unroll
    for (int mf = 0; mf < 2; mf++)
        #pragma unroll
        for (int nf = 0; nf < 4; nf++)
            #pragma unroll
            for (int c = 0; c < 4; c++) acc[mf][nf][c] = 0.f;

    #pragma unroll
    for (int ks = 0; ks < 8; ks++) {
        const int k0 = ks * 16;
        u32 ah[2][4], al[2][4], bh[4][2], bl[4][2];
        #pragma unroll
        for (int mf = 0; mf < 2; mf++) {
            int r0 = wm * 32 + mf * 16;
            ah[mf][0] = *(const u32*)(Ah + (r0 + g    ) * AST + k0 + 2 * t);
            ah[mf][1] = *(const u32*)(Ah + (r0 + g + 8) * AST + k0 + 2 * t);
            ah[mf][2] = *(const u32*)(Ah + (r0 + g    ) * AST + k0 + 2 * t + 8);
            ah[mf][3] = *(const u32*)(Ah + (r0 + g + 8) * AST + k0 + 2 * t + 8);
            al[mf][0] = *(const u32*)(Al + (r0 + g    ) * AST + k0 + 2 * t);
            al[mf][1] = *(const u32*)(Al + (r0 + g + 8) * AST + k0 + 2 * t);
            al[mf][2] = *(const u32*)(Al + (r0 + g    ) * AST + k0 + 2 * t + 8);
            al[mf][3] = *(const u32*)(Al + (r0 + g + 8) * AST + k0 + 2 * t + 8);
        }
        #pragma unroll
        for (int nf = 0; nf < 4; nf++) {
            int n0 = (wn * 32 + nf * 8 + g) * WST;
            bh[nf][0] = *(const u32*)(Wh + n0 + k0 + 2 * t);
            bh[nf][1] = *(const u32*)(Wh + n0 + k0 + 2 * t + 8);
            bl[nf][0] = *(const u32*)(Wl + n0 + k0 + 2 * t);
            bl[nf][1] = *(const u32*)(Wl + n0 + k0 + 2 * t + 8);
        }
        #pragma unroll
        for (int mf = 0; mf < 2; mf++)
            #pragma unroll
            for (int nf = 0; nf < 4; nf++) {
                mma16816(acc[mf][nf], ah[mf], bh[nf]);
                mma16816(acc[mf][nf], al[mf], bh[nf]);
                mma16816(acc[mf][nf], ah[mf], bl[nf]);
            }
    }

    // ---- epilogue ------------------------------------------------------------
    #pragma unroll
    for (int mf = 0; mf < 2; mf++) {
        #pragma unroll
        for (int nf = 0; nf < 4; nf++) {
            int row = rowBlock + wm * 32 + mf * 16 + g;
            int col = wn * 32 + nf * 8 + 2 * t;
            float b0 = 0.f, b1 = 0.f;
            if (bias) { b0 = bias[col]; b1 = bias[col + 1]; }
            float2 v0, v1;
            v0.x = acc[mf][nf][0] + b0; v0.y = acc[mf][nf][1] + b1;
            v1.x = acc[mf][nf][2] + b0; v1.y = acc[mf][nf][3] + b1;
            if (relu) {
                v0.x = fmaxf(v0.x, 0.f); v0.y = fmaxf(v0.y, 0.f);
                v1.x = fmaxf(v1.x, 0.f); v1.y = fmaxf(v1.y, 0.f);
            }
            if (row < n)     *(float2*)(out + (size_t)row * D + col)       = v0;
            if (row + 8 < n) *(float2*)(out + (size_t)(row + 8) * D + col) = v1;
        }
    }
}

// ---------------- CSR gather aggregation -----------------------------------
__global__ void k_gather(const float* __restrict__ xw,
                         float* __restrict__ out,
                         const float* __restrict__ bias, int relu,
                         int n)
{
    int warp = (blockIdx.x * blockDim.x + threadIdx.x) >> 5;
    int lane = threadIdx.x & 31;
    if (warp >= n) return;
    const int d = warp;

    float dis = g_dis[d];
    float dis2 = dis * dis;
    float4 self = ((const float4*)(xw + (size_t)d * D))[lane];
    float4 acc;
    acc.x = self.x * dis2; acc.y = self.y * dis2;
    acc.z = self.z * dis2; acc.w = self.w * dis2;

    int e   = g_rowstart[d];
    int end = g_rowstart[d + 1];

    for (; e + 1 < end; e += 2) {
        int2 e0 = g_csr[e];
        int2 e1 = g_csr[e + 1];
        float c0 = __int_as_float(e0.y);
        float c1 = __int_as_float(e1.y);
        float4 v0 = ((const float4*)(xw + (size_t)e0.x * D))[lane];
        float4 v1 = ((const float4*)(xw + (size_t)e1.x * D))[lane];
        acc.x = fmaf(c0, v0.x, acc.x); acc.y = fmaf(c0, v0.y, acc.y);
        acc.z = fmaf(c0, v0.z, acc.z); acc.w = fmaf(c0, v0.w, acc.w);
        acc.x = fmaf(c1, v1.x, acc.x); acc.y = fmaf(c1, v1.y, acc.y);
        acc.z = fmaf(c1, v1.z, acc.z); acc.w = fmaf(c1, v1.w, acc.w);
    }
    if (e < end) {
        int2 e0 = g_csr[e];
        float c0 = __int_as_float(e0.y);
        float4 v0 = ((const float4*)(xw + (size_t)e0.x * D))[lane];
        acc.x = fmaf(c0, v0.x, acc.x); acc.y = fmaf(c0, v0.y, acc.y);
        acc.z = fmaf(c0, v0.z, acc.z); acc.w = fmaf(c0, v0.w, acc.w);
    }

    const int col = lane * 4;
    acc.x += bias[col]; acc.y += bias[col + 1];
    acc.z += bias[col + 2]; acc.w += bias[col + 3];
    if (relu) {
        acc.x = fmaxf(acc.x, 0.f); acc.y = fmaxf(acc.y, 0.f);
        acc.z = fmaxf(acc.z, 0.f); acc.w = fmaxf(acc.w, 0.f);
    }
    ((float4*)(out + (size_t)d * D))[lane] = acc;
}

// ---------------- launch ---------------------------------------------------
extern "C" void kernel_launch(void* const* d_in, const int* in_sizes, int n_in,
                              void* d_out, int out_size)
{
    const float* x    = (const float*)d_in[0];
    const int*   edge = (const int*)d_in[1];   // int32 or int64 (detected)
    const float* W1 = (const float*)d_in[2]; const float* b1 = (const float*)d_in[3];
    const float* W2 = (const float*)d_in[4]; const float* b2 = (const float*)d_in[5];
    const float* Wv = (const float*)d_in[6]; const float* bv = (const float*)d_in[7];
    const float* Wt = (const float*)d_in[8]; const float* bt = (const float*)d_in[9];

    const int n = in_sizes[0] / D;
    const int E = in_sizes[1] / 2;

    float* out_h = (float*)d_out;
    float* out_v = out_h + (size_t)n * D;
    float* out_t = out_v + (size_t)n * D;

    float* xw = nullptr; cudaGetSymbolAddress((void**)&xw, g_xw);
    float* h  = nullptr; cudaGetSymbolAddress((void**)&h,  g_h);

    cudaFuncSetAttribute(k_gemm_tc, cudaFuncAttributeMaxDynamicSharedMemorySize, SMEM_TC);

    const int TB = 256;
    const int nscan = (n + SCAN_BS - 1) / SCAN_BS;
    const int gemmGrid   = (n + GT - 1) / GT;
    const int gatherGrid = (n + 7) / 8;

    // launches 1-3 small so the conv1 GEMM is the 4th (ncu sample slot)
    k_detect<<<1, 512>>>(edge, 2 * E);
    k_zero<<<(n + TB - 1) / TB, TB>>>(n);
    k_wprep<<<4, 256>>>(W1, W2, Wv, Wt);
    // 4: conv1 GEMM (+ folded degree histogram)
    k_gemm_tc<<<gemmGrid, TB, SMEM_TC>>>(x, n, 0, nullptr, 0, xw, edge, E, 1);
    // normalization + CSR
    k_scan_block<<<nscan, SCAN_BS>>>(n);
    k_scan_tops<<<1, MAX_SCAN_BLOCKS>>>(nscan);
    k_scan_add<<<nscan, SCAN_BS>>>(n, E);
    k_fill<<<(E + TB - 1) / TB, TB>>>(edge, E);
    // conv1 aggregate -> h
    k_gather<<<gatherGrid, TB>>>(xw, h, b1, 1, n);
    // conv2
    k_gemm_tc<<<gemmGrid, TB, SMEM_TC>>>(h, n, 1, nullptr, 0, xw,
                                         nullptr, 0, 0);
    k_gather<<<gatherGrid, TB>>>(xw, out_h, b2, 0, n);
    // heads
    k_gemm_tc<<<gemmGrid, TB, SMEM_TC>>>(out_h, n, 2, bv, 1, out_v,
                                         nullptr, 0, 0);
    k_gemm_tc<<<gemmGrid, TB, SMEM_TC>>>(out_h, n, 3, bt, 1, out_t,
                                         nullptr, 0, 0);
}

// round 15
// speedup vs baseline: 1.4425x; 1.0208x over previous
#include <cuda_runtime.h>
#include <cuda_bf16.h>

typedef unsigned long long u64;
typedef unsigned int u32;

#define MAXN 100000
#define MAXE 1600000
#define D    128
#define SCAN_BS 512
#define MAX_SCAN_BLOCKS 256

#define GT  64                     // GEMM rows per CTA
#define AST 136                    // A smem stride (bf16 elems; 272B -> LDSM 1-phase)
#define WST 136                    // W smem stride
#define AL_OFF (64 * AST)          // elem offsets inside smem
#define WH_OFF (2 * 64 * AST)
#define WL_OFF (2 * 64 * AST + 128 * WST)
#define SMEM_TC ((2 * 64 * AST + 2 * 128 * WST) * 2)   // 104448 B -> 2 CTAs/SM
#define WIMG_ELEMS (128 * WST)

// ---------------- scratch (device globals; fully rewritten each launch) ----
__device__ __align__(16) float g_dis[MAXN];
__device__ __align__(16) float g_xw [(size_t)MAXN * D];
__device__ __align__(16) float g_h  [(size_t)MAXN * D];
__device__ int   g_cnt[MAXN];
__device__ int   g_incl[MAXN];
__device__ int   g_bsum[MAX_SCAN_BLOCKS];
__device__ int   g_rowstart[MAXN + 1];
__device__ int   g_cursor[MAXN];
__device__ __align__(16) int2 g_csr[MAXE];   // (src, coef-bits)
__device__ int g_is64;
// pre-transposed bf16 hi/lo images of W1,W2,Wv,Wt (pairs: 2i=hi, 2i+1=lo)
__device__ __align__(16) __nv_bfloat16 g_wimg[8][WIMG_ELEMS];

// ---------------- edge dtype detection -------------------------------------
__global__ void k_detect(const int* __restrict__ e32, int nwords) {
    __shared__ int any;
    if (threadIdx.x == 0) any = 0;
    __syncthreads();
    int lim = nwords < 4096 ? nwords : 4096;
    for (int w = 1 + 2 * threadIdx.x; w < lim; w += 2 * blockDim.x)
        if (e32[w] != 0) any = 1;
    __syncthreads();
    if (threadIdx.x == 0) g_is64 = any ? 0 : 1;
}
__device__ __forceinline__ int edge_src(const int* e, int E, int i) {
    return g_is64 ? e[2 * (size_t)i] : e[i];
}
__device__ __forceinline__ int edge_dst(const int* e, int E, int i) {
    return g_is64 ? e[2 * ((size_t)E + i)] : e[(size_t)E + i];
}

// ---------------- zero ------------------------------------------------------
__global__ void k_zero(int n) {
    int i = blockIdx.x * blockDim.x + threadIdx.x;
    if (i < n) { g_cnt[i] = 0; g_cursor[i] = 0; }
}

// ---------------- CSR build -------------------------------------------------
__global__ void k_scan_block(int n) {
    __shared__ int sh[SCAN_BS];
    int i = blockIdx.x * SCAN_BS + threadIdx.x;
    int v = (i < n) ? g_cnt[i] : 0;
    if (i < n) g_dis[i] = rsqrtf((float)v + 1.0f);
    sh[threadIdx.x] = v;
    __syncthreads();
    #pragma unroll
    for (int off = 1; off < SCAN_BS; off <<= 1) {
        int t = (threadIdx.x >= off) ? sh[threadIdx.x - off] : 0;
        __syncthreads();
        sh[threadIdx.x] += t;
        __syncthreads();
    }
    if (i < n) g_incl[i] = sh[threadIdx.x];
    if (threadIdx.x == SCAN_BS - 1) g_bsum[blockIdx.x] = sh[threadIdx.x];
}
__global__ void k_scan_tops(int nblocks) {
    __shared__ int sh[MAX_SCAN_BLOCKS];
    int v = (threadIdx.x < nblocks) ? g_bsum[threadIdx.x] : 0;
    sh[threadIdx.x] = v;
    __syncthreads();
    #pragma unroll
    for (int off = 1; off < MAX_SCAN_BLOCKS; off <<= 1) {
        int t = (threadIdx.x >= off) ? sh[threadIdx.x - off] : 0;
        __syncthreads();
        sh[threadIdx.x] += t;
        __syncthreads();
    }
    g_bsum[threadIdx.x] = sh[threadIdx.x] - v;
}
__global__ void k_scan_add(int n, int E) {
    int i = blockIdx.x * SCAN_BS + threadIdx.x;
    if (i < n) {
        int excl = g_incl[i] - g_cnt[i] + g_bsum[blockIdx.x];
        g_rowstart[i] = excl;
        if (i == n - 1) g_rowstart[n] = excl + g_cnt[i];
    }
}
__global__ void k_fill(const int* __restrict__ edge, int E) {
    int i = blockIdx.x * blockDim.x + threadIdx.x;
    if (i < E) {
        int s = edge_src(edge, E, i);
        int d = edge_dst(edge, E, i);
        int pos = g_rowstart[d] + atomicAdd(&g_cursor[d], 1);
        g_csr[pos] = make_int2(s, __float_as_int(g_dis[s] * g_dis[d]));
    }
}

// ---------------- bf16 / mma helpers ----------------------------------------
__device__ __forceinline__ u32 pack_bf2(float x, float y) {
    u32 lo = (u32)__bfloat16_as_ushort(__float2bfloat16_rn(x));
    u32 hi = (u32)__bfloat16_as_ushort(__float2bfloat16_rn(y));
    return lo | (hi << 16);
}
__device__ __forceinline__ void mma16816(float* c, const u32* a, const u32* b) {
    asm volatile(
        "mma.sync.aligned.m16n8k16.row.col.f32.bf16.bf16.f32 "
        "{%0,%1,%2,%3},{%4,%5,%6,%7},{%8,%9},{%0,%1,%2,%3};"
        : "+f"(c[0]), "+f"(c[1]), "+f"(c[2]), "+f"(c[3])
        : "r"(a[0]), "r"(a[1]), "r"(a[2]), "r"(a[3]), "r"(b[0]), "r"(b[1]));
}
#define LDSM4(r0, r1, r2, r3, addr) \
    asm volatile("ldmatrix.sync.aligned.m8n8.x4.shared.b16 {%0,%1,%2,%3}, [%4];" \
                 : "=r"(r0), "=r"(r1), "=r"(r2), "=r"(r3) : "r"(addr))
__device__ __forceinline__ u32 smem_u32(const void* p) {
    return (u32)__cvta_generic_to_shared(p);
}

// ---------------- W prep: fp32 row-major -> transposed bf16 hi/lo images ----
__global__ void k_wprep(const float* __restrict__ Wa, const float* __restrict__ Wb,
                        const float* __restrict__ Wc, const float* __restrict__ Wd)
{
    const float* Ws4[4] = {Wa, Wb, Wc, Wd};
    const float* W = Ws4[blockIdx.x];
    __nv_bfloat16* imgh = g_wimg[2 * blockIdx.x];
    __nv_bfloat16* imgl = g_wimg[2 * blockIdx.x + 1];
    int tid = threadIdx.x;
    #pragma unroll
    for (int i = 0; i < 16; i++) {
        int idx = tid + i * 256;
        int k   = idx >> 5;
        int n0  = (idx & 31) * 4;
        float4 w = ((const float4*)(W + (size_t)k * D))[idx & 31];
        float ws[4] = {w.x, w.y, w.z, w.w};
        #pragma unroll
        for (int j = 0; j < 4; j++) {
            float hi = __bfloat162float(__float2bfloat16_rn(ws[j]));
            imgh[(n0 + j) * WST + k] = __float2bfloat16_rn(hi);
            imgl[(n0 + j) * WST + k] = __float2bfloat16_rn(ws[j] - hi);
        }
    }
}

// ---------------- tensor-core GEMM (bf16 3-term split, ldmatrix) ------------
// out = f(A @ W + bias).  64 rows x 128 cols x K=128, 256 threads,
// 2 CTAs/SM. Warp (wm=wid>>2, wn=wid&3) tile 32x32: 2x4 m16n8k16 frags,
// 3 terms (AhBh + AlBh + AhBl). Fragments via ldmatrix.x4 (8 LDSM/warp-ks).
__global__ void __launch_bounds__(256, 2)
k_gemm_tc(const float* __restrict__ A, int n, int wsel,
          const float* __restrict__ bias, int relu, float* __restrict__ out,
          const int* __restrict__ edge, int E, int hist)
{
    extern __shared__ __align__(16) __nv_bfloat16 sm[];
    __nv_bfloat16* Ah = sm;
    __nv_bfloat16* Al = sm + AL_OFF;
    __nv_bfloat16* Wh = sm + WH_OFF;

    const int tid = threadIdx.x;
    const int rowBlock = blockIdx.x * GT;

    // folded degree histogram (fire-and-forget REDs)
    if (hist) {
        int per  = (E + gridDim.x - 1) / gridDim.x;
        int base = blockIdx.x * per;
        int lim  = base + per; if (lim > E) lim = E;
        for (int i = base + tid; i < lim; i += 256)
            atomicAdd(&g_cnt[edge_dst(edge, E, i)], 1);
    }

    // ---- fill A hi/lo (row-major, stride AST), zero OOB rows ---------------
    #pragma unroll
    for (int i = 0; i < 8; i++) {
        int idx = tid + i * 256;
        int r   = idx >> 5;
        int c4  = idx & 31;
        int grow = rowBlock + r;
        float4 v = make_float4(0.f, 0.f, 0.f, 0.f);
        if (grow < n) v = ((const float4*)(A + (size_t)grow * D))[c4];
        float hx = __bfloat162float(__float2bfloat16_rn(v.x));
        float hy = __bfloat162float(__float2bfloat16_rn(v.y));
        float hz = __bfloat162float(__float2bfloat16_rn(v.z));
        float hw = __bfloat162float(__float2bfloat16_rn(v.w));
        u32* ph = (u32*)(Ah + r * AST + c4 * 4);
        u32* pl = (u32*)(Al + r * AST + c4 * 4);
        ph[0] = pack_bf2(hx, hy);             ph[1] = pack_bf2(hz, hw);
        pl[0] = pack_bf2(v.x - hx, v.y - hy); pl[1] = pack_bf2(v.z - hz, v.w - hw);
    }
    // ---- copy W hi/lo images (verbatim) ------------------------------------
    {
        const float4* src = (const float4*)g_wimg[2 * wsel];
        float4* dst = (float4*)Wh;            // Wh then Wl contiguous
        #pragma unroll
        for (int i = 0; i < 17; i++)
            dst[tid + i * 256] = src[tid + i * 256];
    }
    __syncthreads();

    const int wid  = tid >> 5, lane = tid & 31;
    const int wm = wid >> 2;        // rows wm*32
    const int wn = wid & 3;         // cols wn*32
    const int g  = lane >> 2, t = lane & 3;

    // ldmatrix per-thread addresses (byte offsets in shared space)
    const u32 smbase = smem_u32(sm);
    // A: lanes 0-15 -> rows lr at k0; lanes 16-31 -> rows lr at k0+8
    const int lr = lane & 15;
    const int kh = (lane >> 4) * 8;
    u32 aH0 = smbase + ((wm * 32 + lr) * AST + kh) * 2;           // mf=0 hi
    u32 aH1 = aH0 + 16 * AST * 2;                                 // mf=1 hi
    u32 aL0 = aH0 + AL_OFF * 2;                                   // mf=0 lo
    u32 aL1 = aH1 + AL_OFF * 2;
    // B: x4 packs frag pair (nf, nf+1): sel=lane>>3: {n+bl,k0},{n+bl,k0+8},
    //    {n+8+bl,k0},{n+8+bl,k0+8}
    const int bl8 = lane & 7;
    const int sel = lane >> 3;
    const int nse = (sel >> 1) * 8;
    const int kse = (sel & 1) * 8;
    u32 bH0 = smbase + WH_OFF * 2 +
              ((wn * 32 + nse + bl8) * WST + kse) * 2;            // frags 0,1
    u32 bH1 = bH0 + 16 * WST * 2;                                 // frags 2,3
    u32 bL0 = bH0 + 128 * WST * 2;                                // lo images
    u32 bL1 = bH1 + 128 * WST * 2;

    float acc[2][4][4];
    #pragma unroll
    for (int mf = 0; mf < 2; mf++)
        #pragma unroll
        for (int nf = 0; nf < 4; nf++)
            #pragma unroll
            for (int c = 0; c < 4; c++) acc[mf][nf][c] = 0.f;

    #pragma unroll
    for (int ks = 0; ks < 8; ks++) {
        const u32 kb = ks * 32;        // 16 bf16 = 32 bytes per ks
        u32 ah[2][4], al[2][4], bh[8], blo[8];
        LDSM4(ah[0][0], ah[0][1], ah[0][2], ah[0][3], aH0 + kb);
        LDSM4(ah[1][0], ah[1][1], ah[1][2], ah[1][3], aH1 + kb);
        LDSM4(bh[0], bh[1], bh[2], bh[3], bH0 + kb);
        LDSM4(bh[4], bh[5], bh[6], bh[7], bH1 + kb);
        // term 1: Ah*Bh (lo loads issued after, overlap with these mmas)
        LDSM4(al[0][0], al[0][1], al[0][2], al[0][3], aL0 + kb);
        LDSM4(al[1][0], al[1][1], al[1][2], al[1][3], aL1 + kb);
        LDSM4(blo[0], blo[1], blo[2], blo[3], bL0 + kb);
        LDSM4(blo[4], blo[5], blo[6], blo[7], bL1 + kb);
        #pragma unroll
        for (int mf = 0; mf < 2; mf++)
            #pragma unroll
            for (int nf = 0; nf < 4; nf++)
                mma16816(acc[mf][nf], ah[mf], bh + 2 * nf);
        // term 2: Al*Bh
        #pragma unroll
        for (int mf = 0; mf < 2; mf++)
            #pragma unroll
            for (int nf = 0; nf < 4; nf++)
                mma16816(acc[mf][nf], al[mf], bh + 2 * nf);
        // term 3: Ah*Bl
        #pragma unroll
        for (int mf = 0; mf < 2; mf++)
            #pragma unroll
            for (int nf = 0; nf < 4; nf++)
                mma16816(acc[mf][nf], ah[mf], blo + 2 * nf);
    }

    // ---- epilogue ------------------------------------------------------------
    #pragma unroll
    for (int mf = 0; mf < 2; mf++) {
        #pragma unroll
        for (int nf = 0; nf < 4; nf++) {
            int row = rowBlock + wm * 32 + mf * 16 + g;
            int col = wn * 32 + nf * 8 + 2 * t;
            float b0 = 0.f, b1 = 0.f;
            if (bias) { b0 = bias[col]; b1 = bias[col + 1]; }
            float2 v0, v1;
            v0.x = acc[mf][nf][0] + b0; v0.y = acc[mf][nf][1] + b1;
            v1.x = acc[mf][nf][2] + b0; v1.y = acc[mf][nf][3] + b1;
            if (relu) {
                v0.x = fmaxf(v0.x, 0.f); v0.y = fmaxf(v0.y, 0.f);
                v1.x = fmaxf(v1.x, 0.f); v1.y = fmaxf(v1.y, 0.f);
            }
            if (row < n)     *(float2*)(out + (size_t)row * D + col)       = v0;
            if (row + 8 < n) *(float2*)(out + (size_t)(row + 8) * D + col) = v1;
        }
    }
}

// ---------------- CSR gather aggregation -----------------------------------
__global__ void k_gather(const float* __restrict__ xw,
                         float* __restrict__ out,
                         const float* __restrict__ bias, int relu,
                         int n)
{
    int warp = (blockIdx.x * blockDim.x + threadIdx.x) >> 5;
    int lane = threadIdx.x & 31;
    if (warp >= n) return;
    const int d = warp;

    float dis = g_dis[d];
    float dis2 = dis * dis;
    float4 self = ((const float4*)(xw + (size_t)d * D))[lane];
    float4 acc;
    acc.x = self.x * dis2; acc.y = self.y * dis2;
    acc.z = self.z * dis2; acc.w = self.w * dis2;

    int e   = g_rowstart[d];
    int end = g_rowstart[d + 1];

    for (; e + 1 < end; e += 2) {
        int2 e0 = g_csr[e];
        int2 e1 = g_csr[e + 1];
        float c0 = __int_as_float(e0.y);
        float c1 = __int_as_float(e1.y);
        float4 v0 = ((const float4*)(xw + (size_t)e0.x * D))[lane];
        float4 v1 = ((const float4*)(xw + (size_t)e1.x * D))[lane];
        acc.x = fmaf(c0, v0.x, acc.x); acc.y = fmaf(c0, v0.y, acc.y);
        acc.z = fmaf(c0, v0.z, acc.z); acc.w = fmaf(c0, v0.w, acc.w);
        acc.x = fmaf(c1, v1.x, acc.x); acc.y = fmaf(c1, v1.y, acc.y);
        acc.z = fmaf(c1, v1.z, acc.z); acc.w = fmaf(c1, v1.w, acc.w);
    }
    if (e < end) {
        int2 e0 = g_csr[e];
        float c0 = __int_as_float(e0.y);
        float4 v0 = ((const float4*)(xw + (size_t)e0.x * D))[lane];
        acc.x = fmaf(c0, v0.x, acc.x); acc.y = fmaf(c0, v0.y, acc.y);
        acc.z = fmaf(c0, v0.z, acc.z); acc.w = fmaf(c0, v0.w, acc.w);
    }

    const int col = lane * 4;
    acc.x += bias[col]; acc.y += bias[col + 1];
    acc.z += bias[col + 2]; acc.w += bias[col + 3];
    if (relu) {
        acc.x = fmaxf(acc.x, 0.f); acc.y = fmaxf(acc.y, 0.f);
        acc.z = fmaxf(acc.z, 0.f); acc.w = fmaxf(acc.w, 0.f);
    }
    ((float4*)(out + (size_t)d * D))[lane] = acc;
}

// ---------------- launch ---------------------------------------------------
extern "C" void kernel_launch(void* const* d_in, const int* in_sizes, int n_in,
                              void* d_out, int out_size)
{
    const float* x    = (const float*)d_in[0];
    const int*   edge = (const int*)d_in[1];   // int32 or int64 (detected)
    const float* W1 = (const float*)d_in[2]; const float* b1 = (const float*)d_in[3];
    const float* W2 = (const float*)d_in[4]; const float* b2 = (const float*)d_in[5];
    const float* Wv = (const float*)d_in[6]; const float* bv = (const float*)d_in[7];
    const float* Wt = (const float*)d_in[8]; const float* bt = (const float*)d_in[9];

    const int n = in_sizes[0] / D;
    const int E = in_sizes[1] / 2;

    float* out_h = (float*)d_out;
    float* out_v = out_h + (size_t)n * D;
    float* out_t = out_v + (size_t)n * D;

    float* xw = nullptr; cudaGetSymbolAddress((void**)&xw, g_xw);
    float* h  = nullptr; cudaGetSymbolAddress((void**)&h,  g_h);

    cudaFuncSetAttribute(k_gemm_tc, cudaFuncAttributeMaxDynamicSharedMemorySize, SMEM_TC);

    const int TB = 256;
    const int nscan = (n + SCAN_BS - 1) / SCAN_BS;
    const int gemmGrid   = (n + GT - 1) / GT;
    const int gatherGrid = (n + 7) / 8;

    // launches 1-3 small so the conv1 GEMM is the 4th (ncu sample slot)
    k_detect<<<1, 512>>>(edge, 2 * E);
    k_zero<<<(n + TB - 1) / TB, TB>>>(n);
    k_wprep<<<4, 256>>>(W1, W2, Wv, Wt);
    // 4: conv1 GEMM (+ folded degree histogram)
    k_gemm_tc<<<gemmGrid, TB, SMEM_TC>>>(x, n, 0, nullptr, 0, xw, edge, E, 1);
    // normalization + CSR
    k_scan_block<<<nscan, SCAN_BS>>>(n);
    k_scan_tops<<<1, MAX_SCAN_BLOCKS>>>(nscan);
    k_scan_add<<<nscan, SCAN_BS>>>(n, E);
    k_fill<<<(E + TB - 1) / TB, TB>>>(edge, E);
    // conv1 aggregate -> h
    k_gather<<<gatherGrid, TB>>>(xw, h, b1, 1, n);
    // conv2
    k_gemm_tc<<<gemmGrid, TB, SMEM_TC>>>(h, n, 1, nullptr, 0, xw,
                                         nullptr, 0, 0);
    k_gather<<<gatherGrid, TB>>>(xw, out_h, b2, 0, n);
    // heads
    k_gemm_tc<<<gemmGrid, TB, SMEM_TC>>>(out_h, n, 2, bv, 1, out_v,
                                         nullptr, 0, 0);
    k_gemm_tc<<<gemmGrid, TB, SMEM_TC>>>(out_h, n, 3, bt, 1, out_t,
                                         nullptr, 0, 0);
}

// round 16
// speedup vs baseline: 1.4654x; 1.0159x over previous
#include <cuda_runtime.h>
#include <cuda_bf16.h>

typedef unsigned long long u64;
typedef unsigned int u32;

#define MAXN 100000
#define MAXE 1600000
#define D    128
#define SCAN_BS 512
#define MAX_SCAN_BLOCKS 256

#define GT  64                     // GEMM rows per tile
#define AST 136                    // A smem stride (bf16 elems)
#define WST 136                    // W smem stride
#define AL_OFF (64 * AST)
#define WH_OFF (2 * 64 * AST)
#define SMEM_TC ((2 * 64 * AST + 2 * 128 * WST) * 2)   // 104448 B -> 2 CTAs/SM
#define WIMG_ELEMS (128 * WST)
#define GEMM_GRID 296              // 2 CTAs/SM x 148 SMs (persistent)

// ---------------- scratch (device globals; fully rewritten each launch) ----
__device__ __align__(16) float g_dis[MAXN];
__device__ __align__(16) float g_xw [(size_t)MAXN * D];
__device__ __align__(16) float g_h  [(size_t)MAXN * D];
__device__ int   g_cnt[MAXN];
__device__ int   g_incl[MAXN];
__device__ int   g_bsum[MAX_SCAN_BLOCKS];
__device__ int   g_rowstart[MAXN + 1];
__device__ int   g_cursor[MAXN];
__device__ __align__(16) int2 g_csr[MAXE];   // (src, coef-bits)
__device__ int g_is64;
__device__ __align__(16) __nv_bfloat16 g_wimg[8][WIMG_ELEMS];

// ---------------- edge dtype detection -------------------------------------
__global__ void k_detect(const int* __restrict__ e32, int nwords) {
    __shared__ int any;
    if (threadIdx.x == 0) any = 0;
    __syncthreads();
    int lim = nwords < 4096 ? nwords : 4096;
    for (int w = 1 + 2 * threadIdx.x; w < lim; w += 2 * blockDim.x)
        if (e32[w] != 0) any = 1;
    __syncthreads();
    if (threadIdx.x == 0) g_is64 = any ? 0 : 1;
}
__device__ __forceinline__ int edge_src(const int* e, int E, int i) {
    return g_is64 ? e[2 * (size_t)i] : e[i];
}
__device__ __forceinline__ int edge_dst(const int* e, int E, int i) {
    return g_is64 ? e[2 * ((size_t)E + i)] : e[(size_t)E + i];
}

// ---------------- zero ------------------------------------------------------
__global__ void k_zero(int n) {
    int i = blockIdx.x * blockDim.x + threadIdx.x;
    if (i < n) { g_cnt[i] = 0; g_cursor[i] = 0; }
}

// ---------------- CSR build -------------------------------------------------
__global__ void k_scan_block(int n) {
    __shared__ int sh[SCAN_BS];
    int i = blockIdx.x * SCAN_BS + threadIdx.x;
    int v = (i < n) ? g_cnt[i] : 0;
    if (i < n) g_dis[i] = rsqrtf((float)v + 1.0f);
    sh[threadIdx.x] = v;
    __syncthreads();
    #pragma unroll
    for (int off = 1; off < SCAN_BS; off <<= 1) {
        int t = (threadIdx.x >= off) ? sh[threadIdx.x - off] : 0;
        __syncthreads();
        sh[threadIdx.x] += t;
        __syncthreads();
    }
    if (i < n) g_incl[i] = sh[threadIdx.x];
    if (threadIdx.x == SCAN_BS - 1) g_bsum[blockIdx.x] = sh[threadIdx.x];
}
__global__ void k_scan_tops(int nblocks) {
    __shared__ int sh[MAX_SCAN_BLOCKS];
    int v = (threadIdx.x < nblocks) ? g_bsum[threadIdx.x] : 0;
    sh[threadIdx.x] = v;
    __syncthreads();
    #pragma unroll
    for (int off = 1; off < MAX_SCAN_BLOCKS; off <<= 1) {
        int t = (threadIdx.x >= off) ? sh[threadIdx.x - off] : 0;
        __syncthreads();
        sh[threadIdx.x] += t;
        __syncthreads();
    }
    g_bsum[threadIdx.x] = sh[threadIdx.x] - v;
}
__global__ void k_scan_add(int n, int E) {
    int i = blockIdx.x * SCAN_BS + threadIdx.x;
    if (i < n) {
        int excl = g_incl[i] - g_cnt[i] + g_bsum[blockIdx.x];
        g_rowstart[i] = excl;
        if (i == n - 1) g_rowstart[n] = excl + g_cnt[i];
    }
}
__global__ void k_fill(const int* __restrict__ edge, int E) {
    int i = blockIdx.x * blockDim.x + threadIdx.x;
    if (i < E) {
        int s = edge_src(edge, E, i);
        int d = edge_dst(edge, E, i);
        int pos = g_rowstart[d] + atomicAdd(&g_cursor[d], 1);
        g_csr[pos] = make_int2(s, __float_as_int(g_dis[s] * g_dis[d]));
    }
}

// ---------------- bf16 / mma helpers ----------------------------------------
__device__ __forceinline__ u32 pack_bf2(float x, float y) {
    u32 lo = (u32)__bfloat16_as_ushort(__float2bfloat16_rn(x));
    u32 hi = (u32)__bfloat16_as_ushort(__float2bfloat16_rn(y));
    return lo | (hi << 16);
}
__device__ __forceinline__ void mma16816(float* c, const u32* a, const u32* b) {
    asm volatile(
        "mma.sync.aligned.m16n8k16.row.col.f32.bf16.bf16.f32 "
        "{%0,%1,%2,%3},{%4,%5,%6,%7},{%8,%9},{%0,%1,%2,%3};"
        : "+f"(c[0]), "+f"(c[1]), "+f"(c[2]), "+f"(c[3])
        : "r"(a[0]), "r"(a[1]), "r"(a[2]), "r"(a[3]), "r"(b[0]), "r"(b[1]));
}
#define LDSM4(r0, r1, r2, r3, addr) \
    asm volatile("ldmatrix.sync.aligned.m8n8.x4.shared.b16 {%0,%1,%2,%3}, [%4];" \
                 : "=r"(r0), "=r"(r1), "=r"(r2), "=r"(r3) : "r"(addr))
__device__ __forceinline__ u32 smem_u32(const void* p) {
    return (u32)__cvta_generic_to_shared(p);
}

// ---------------- W prep: fp32 row-major -> transposed bf16 hi/lo images ----
__global__ void k_wprep(const float* __restrict__ Wa, const float* __restrict__ Wb,
                        const float* __restrict__ Wc, const float* __restrict__ Wd)
{
    const float* Ws4[4] = {Wa, Wb, Wc, Wd};
    const float* W = Ws4[blockIdx.x];
    __nv_bfloat16* imgh = g_wimg[2 * blockIdx.x];
    __nv_bfloat16* imgl = g_wimg[2 * blockIdx.x + 1];
    int tid = threadIdx.x;
    #pragma unroll
    for (int i = 0; i < 16; i++) {
        int idx = tid + i * 256;
        int k   = idx >> 5;
        int n0  = (idx & 31) * 4;
        float4 w = ((const float4*)(W + (size_t)k * D))[idx & 31];
        float ws[4] = {w.x, w.y, w.z, w.w};
        #pragma unroll
        for (int j = 0; j < 4; j++) {
            float hi = __bfloat162float(__float2bfloat16_rn(ws[j]));
            imgh[(n0 + j) * WST + k] = __float2bfloat16_rn(hi);
            imgl[(n0 + j) * WST + k] = __float2bfloat16_rn(ws[j] - hi);
        }
    }
}

// ---------------- persistent tensor-core GEMM (bf16 3-term split) -----------
// out = f(A @ W + bias). Grid = GEMM_GRID persistent CTAs; each loads W ONCE
// then grid-strides over 64-row tiles: fill A -> sync -> mma+epi -> sync.
__global__ void __launch_bounds__(256, 2)
k_gemm_tc(const float* __restrict__ A, int n, int wsel,
          const float* __restrict__ bias, int relu, float* __restrict__ out,
          const int* __restrict__ edge, int E, int hist)
{
    extern __shared__ __align__(16) __nv_bfloat16 sm[];
    __nv_bfloat16* Ah = sm;
    __nv_bfloat16* Al = sm + AL_OFF;
    __nv_bfloat16* Wh = sm + WH_OFF;

    const int tid = threadIdx.x;

    // folded degree histogram (fire-and-forget REDs; conv1 only)
    if (hist) {
        int per  = (E + gridDim.x - 1) / gridDim.x;
        int base = blockIdx.x * per;
        int lim  = base + per; if (lim > E) lim = E;
        for (int i = base + tid; i < lim; i += 256)
            atomicAdd(&g_cnt[edge_dst(edge, E, i)], 1);
    }

    // ---- copy W hi/lo image ONCE (68KB from L2) -----------------------------
    {
        const float4* src = (const float4*)g_wimg[2 * wsel];
        float4* dst = (float4*)Wh;
        #pragma unroll
        for (int i = 0; i < 17; i++)
            dst[tid + i * 256] = src[tid + i * 256];
    }

    const int wid  = tid >> 5, lane = tid & 31;
    const int wm = wid >> 2;
    const int wn = wid & 3;
    const int g  = lane >> 2, t = lane & 3;

    const u32 smbase = smem_u32(sm);
    const int lr = lane & 15;
    const int kh = (lane >> 4) * 8;
    const u32 aH0 = smbase + ((wm * 32 + lr) * AST + kh) * 2;
    const u32 aH1 = aH0 + 16 * AST * 2;
    const u32 aL0 = aH0 + AL_OFF * 2;
    const u32 aL1 = aH1 + AL_OFF * 2;
    const int bl8 = lane & 7;
    const int sel = lane >> 3;
    const int nse = (sel >> 1) * 8;
    const int kse = (sel & 1) * 8;
    const u32 bH0 = smbase + WH_OFF * 2 +
                    ((wn * 32 + nse + bl8) * WST + kse) * 2;
    const u32 bH1 = bH0 + 16 * WST * 2;
    const u32 bL0 = bH0 + 128 * WST * 2;
    const u32 bL1 = bH1 + 128 * WST * 2;

    const int nblocks = (n + GT - 1) / GT;
    for (int rb = blockIdx.x; rb < nblocks; rb += gridDim.x) {
        const int rowBlock = rb * GT;

        // ---- fill A hi/lo, zero OOB rows ------------------------------------
        #pragma unroll
        for (int i = 0; i < 8; i++) {
            int idx = tid + i * 256;
            int r   = idx >> 5;
            int c4  = idx & 31;
            int grow = rowBlock + r;
            float4 v = make_float4(0.f, 0.f, 0.f, 0.f);
            if (grow < n) v = ((const float4*)(A + (size_t)grow * D))[c4];
            float hx = __bfloat162float(__float2bfloat16_rn(v.x));
            float hy = __bfloat162float(__float2bfloat16_rn(v.y));
            float hz = __bfloat162float(__float2bfloat16_rn(v.z));
            float hw = __bfloat162float(__float2bfloat16_rn(v.w));
            u32* ph = (u32*)(Ah + r * AST + c4 * 4);
            u32* pl = (u32*)(Al + r * AST + c4 * 4);
            ph[0] = pack_bf2(hx, hy);             ph[1] = pack_bf2(hz, hw);
            pl[0] = pack_bf2(v.x - hx, v.y - hy); pl[1] = pack_bf2(v.z - hz, v.w - hw);
        }
        __syncthreads();

        float acc[2][4][4];
        #pragma unroll
        for (int mf = 0; mf < 2; mf++)
            #pragma unroll
            for (int nf = 0; nf < 4; nf++)
                #pragma unroll
                for (int c = 0; c < 4; c++) acc[mf][nf][c] = 0.f;

        #pragma unroll
        for (int ks = 0; ks < 8; ks++) {
            const u32 kb = ks * 32;
            u32 ah[2][4], al[2][4], bh[8], blo[8];
            LDSM4(ah[0][0], ah[0][1], ah[0][2], ah[0][3], aH0 + kb);
            LDSM4(ah[1][0], ah[1][1], ah[1][2], ah[1][3], aH1 + kb);
            LDSM4(bh[0], bh[1], bh[2], bh[3], bH0 + kb);
            LDSM4(bh[4], bh[5], bh[6], bh[7], bH1 + kb);
            LDSM4(al[0][0], al[0][1], al[0][2], al[0][3], aL0 + kb);
            LDSM4(al[1][0], al[1][1], al[1][2], al[1][3], aL1 + kb);
            LDSM4(blo[0], blo[1], blo[2], blo[3], bL0 + kb);
            LDSM4(blo[4], blo[5], blo[6], blo[7], bL1 + kb);
            #pragma unroll
            for (int mf = 0; mf < 2; mf++)
                #pragma unroll
                for (int nf = 0; nf < 4; nf++)
                    mma16816(acc[mf][nf], ah[mf], bh + 2 * nf);
            #pragma unroll
            for (int mf = 0; mf < 2; mf++)
                #pragma unroll
                for (int nf = 0; nf < 4; nf++)
                    mma16816(acc[mf][nf], al[mf], bh + 2 * nf);
            #pragma unroll
            for (int mf = 0; mf < 2; mf++)
                #pragma unroll
                for (int nf = 0; nf < 4; nf++)
                    mma16816(acc[mf][nf], ah[mf], blo + 2 * nf);
        }

        // ---- epilogue ---------------------------------------------------------
        #pragma unroll
        for (int mf = 0; mf < 2; mf++) {
            #pragma unroll
            for (int nf = 0; nf < 4; nf++) {
                int row = rowBlock + wm * 32 + mf * 16 + g;
                int col = wn * 32 + nf * 8 + 2 * t;
                float b0 = 0.f, b1 = 0.f;
                if (bias) { b0 = bias[col]; b1 = bias[col + 1]; }
                float2 v0, v1;
                v0.x = acc[mf][nf][0] + b0; v0.y = acc[mf][nf][1] + b1;
                v1.x = acc[mf][nf][2] + b0; v1.y = acc[mf][nf][3] + b1;
                if (relu) {
                    v0.x = fmaxf(v0.x, 0.f); v0.y = fmaxf(v0.y, 0.f);
                    v1.x = fmaxf(v1.x, 0.f); v1.y = fmaxf(v1.y, 0.f);
                }
                if (row < n)     *(float2*)(out + (size_t)row * D + col)       = v0;
                if (row + 8 < n) *(float2*)(out + (size_t)(row + 8) * D + col) = v1;
            }
        }
        __syncthreads();   // before next tile's A fill overwrites Ah/Al
    }
}

// ---------------- CSR gather aggregation -----------------------------------
__global__ void k_gather(const float* __restrict__ xw,
                         float* __restrict__ out,
                         const float* __restrict__ bias, int relu,
                         int n)
{
    int warp = (blockIdx.x * blockDim.x + threadIdx.x) >> 5;
    int lane = threadIdx.x & 31;
    if (warp >= n) return;
    const int d = warp;

    float dis = g_dis[d];
    float dis2 = dis * dis;
    float4 self = ((const float4*)(xw + (size_t)d * D))[lane];
    float4 acc;
    acc.x = self.x * dis2; acc.y = self.y * dis2;
    acc.z = self.z * dis2; acc.w = self.w * dis2;

    int e   = g_rowstart[d];
    int end = g_rowstart[d + 1];

    for (; e + 1 < end; e += 2) {
        int2 e0 = g_csr[e];
        int2 e1 = g_csr[e + 1];
        float c0 = __int_as_float(e0.y);
        float c1 = __int_as_float(e1.y);
        float4 v0 = ((const float4*)(xw + (size_t)e0.x * D))[lane];
        float4 v1 = ((const float4*)(xw + (size_t)e1.x * D))[lane];
        acc.x = fmaf(c0, v0.x, acc.x); acc.y = fmaf(c0, v0.y, acc.y);
        acc.z = fmaf(c0, v0.z, acc.z); acc.w = fmaf(c0, v0.w, acc.w);
        acc.x = fmaf(c1, v1.x, acc.x); acc.y = fmaf(c1, v1.y, acc.y);
        acc.z = fmaf(c1, v1.z, acc.z); acc.w = fmaf(c1, v1.w, acc.w);
    }
    if (e < end) {
        int2 e0 = g_csr[e];
        float c0 = __int_as_float(e0.y);
        float4 v0 = ((const float4*)(xw + (size_t)e0.x * D))[lane];
        acc.x = fmaf(c0, v0.x, acc.x); acc.y = fmaf(c0, v0.y, acc.y);
        acc.z = fmaf(c0, v0.z, acc.z); acc.w = fmaf(c0, v0.w, acc.w);
    }

    const int col = lane * 4;
    acc.x += bias[col]; acc.y += bias[col + 1];
    acc.z += bias[col + 2]; acc.w += bias[col + 3];
    if (relu) {
        acc.x = fmaxf(acc.x, 0.f); acc.y = fmaxf(acc.y, 0.f);
        acc.z = fmaxf(acc.z, 0.f); acc.w = fmaxf(acc.w, 0.f);
    }
    ((float4*)(out + (size_t)d * D))[lane] = acc;
}

// ---------------- launch ---------------------------------------------------
extern "C" void kernel_launch(void* const* d_in, const int* in_sizes, int n_in,
                              void* d_out, int out_size)
{
    const float* x    = (const float*)d_in[0];
    const int*   edge = (const int*)d_in[1];   // int32 or int64 (detected)
    const float* W1 = (const float*)d_in[2]; const float* b1 = (const float*)d_in[3];
    const float* W2 = (const float*)d_in[4]; const float* b2 = (const float*)d_in[5];
    const float* Wv = (const float*)d_in[6]; const float* bv = (const float*)d_in[7];
    const float* Wt = (const float*)d_in[8]; const float* bt = (const float*)d_in[9];

    const int n = in_sizes[0] / D;
    const int E = in_sizes[1] / 2;

    float* out_h = (float*)d_out;
    float* out_v = out_h + (size_t)n * D;
    float* out_t = out_v + (size_t)n * D;

    float* xw = nullptr; cudaGetSymbolAddress((void**)&xw, g_xw);
    float* h  = nullptr; cudaGetSymbolAddress((void**)&h,  g_h);

    cudaFuncSetAttribute(k_gemm_tc, cudaFuncAttributeMaxDynamicSharedMemorySize, SMEM_TC);

    const int TB = 256;
    const int nscan = (n + SCAN_BS - 1) / SCAN_BS;
    const int gatherGrid = (n + 7) / 8;

    // launches 1-3 small so the conv1 GEMM is the 4th (ncu sample slot)
    k_detect<<<1, 512>>>(edge, 2 * E);
    k_zero<<<(n + TB - 1) / TB, TB>>>(n);
    k_wprep<<<4, 256>>>(W1, W2, Wv, Wt);
    // 4: conv1 GEMM (persistent; + folded degree histogram)
    k_gemm_tc<<<GEMM_GRID, TB, SMEM_TC>>>(x, n, 0, nullptr, 0, xw, edge, E, 1);
    // normalization + CSR
    k_scan_block<<<nscan, SCAN_BS>>>(n);
    k_scan_tops<<<1, MAX_SCAN_BLOCKS>>>(nscan);
    k_scan_add<<<nscan, SCAN_BS>>>(n, E);
    k_fill<<<(E + TB - 1) / TB, TB>>>(edge, E);
    // conv1 aggregate -> h
    k_gather<<<gatherGrid, TB>>>(xw, h, b1, 1, n);
    // conv2
    k_gemm_tc<<<GEMM_GRID, TB, SMEM_TC>>>(h, n, 1, nullptr, 0, xw,
                                          nullptr, 0, 0);
    k_gather<<<gatherGrid, TB>>>(xw, out_h, b2, 0, n);
    // heads
    k_gemm_tc<<<GEMM_GRID, TB, SMEM_TC>>>(out_h, n, 2, bv, 1, out_v,
                                          nullptr, 0, 0);
    k_gemm_tc<<<GEMM_GRID, TB, SMEM_TC>>>(out_h, n, 3, bt, 1, out_t,
                                          nullptr, 0, 0);
}

// round 17
// speedup vs baseline: 1.4719x; 1.0044x over previous
#include <cuda_runtime.h>
#include <cuda_bf16.h>

typedef unsigned long long u64;
typedef unsigned int u32;

#define MAXN 100000
#define MAXE 1600000
#define D    128
#define SCAN_BS 512
#define MAX_SCAN_BLOCKS 256

#define GT  64                     // GEMM rows per tile
#define AST 136                    // A smem stride (bf16 elems)
#define WST 136                    // W smem stride
#define AL_OFF (64 * AST)
#define WH_OFF (2 * 64 * AST)
#define SMEM_TC ((2 * 64 * AST + 2 * 128 * WST) * 2)   // 104448 B -> 2 CTAs/SM
#define WIMG_ELEMS (128 * WST)
#define GEMM_GRID 296              // 2 CTAs/SM x 148 SMs (persistent)

// ---------------- scratch (device globals; fully rewritten each launch) ----
__device__ __align__(16) float g_dis[MAXN];
__device__ __align__(16) float g_xw [(size_t)MAXN * D];
__device__ __align__(16) float g_h  [(size_t)MAXN * D];
__device__ int   g_cnt[MAXN];
__device__ int   g_incl[MAXN];
__device__ int   g_bsum[MAX_SCAN_BLOCKS];
__device__ int   g_rowstart[MAXN + 1];
__device__ int   g_cursor[MAXN];
__device__ __align__(16) int2 g_csr[MAXE];   // (src, coef-bits)
__device__ int g_is64;
__device__ __align__(16) __nv_bfloat16 g_wimg[8][WIMG_ELEMS];

// ---------------- edge dtype detection -------------------------------------
__global__ void k_detect(const int* __restrict__ e32, int nwords) {
    __shared__ int any;
    if (threadIdx.x == 0) any = 0;
    __syncthreads();
    int lim = nwords < 4096 ? nwords : 4096;
    for (int w = 1 + 2 * threadIdx.x; w < lim; w += 2 * blockDim.x)
        if (e32[w] != 0) any = 1;
    __syncthreads();
    if (threadIdx.x == 0) g_is64 = any ? 0 : 1;
}
__device__ __forceinline__ int edge_src(const int* e, int E, int i) {
    return g_is64 ? e[2 * (size_t)i] : e[i];
}
__device__ __forceinline__ int edge_dst(const int* e, int E, int i) {
    return g_is64 ? e[2 * ((size_t)E + i)] : e[(size_t)E + i];
}

// ---------------- zero ------------------------------------------------------
__global__ void k_zero(int n) {
    int i = blockIdx.x * blockDim.x + threadIdx.x;
    if (i < n) { g_cnt[i] = 0; g_cursor[i] = 0; }
}

// ---------------- CSR build -------------------------------------------------
__global__ void k_scan_block(int n) {
    __shared__ int sh[SCAN_BS];
    int i = blockIdx.x * SCAN_BS + threadIdx.x;
    int v = (i < n) ? g_cnt[i] : 0;
    if (i < n) g_dis[i] = rsqrtf((float)v + 1.0f);
    sh[threadIdx.x] = v;
    __syncthreads();
    #pragma unroll
    for (int off = 1; off < SCAN_BS; off <<= 1) {
        int t = (threadIdx.x >= off) ? sh[threadIdx.x - off] : 0;
        __syncthreads();
        sh[threadIdx.x] += t;
        __syncthreads();
    }
    if (i < n) g_incl[i] = sh[threadIdx.x];
    if (threadIdx.x == SCAN_BS - 1) g_bsum[blockIdx.x] = sh[threadIdx.x];
}
__global__ void k_scan_tops(int nblocks) {
    __shared__ int sh[MAX_SCAN_BLOCKS];
    int v = (threadIdx.x < nblocks) ? g_bsum[threadIdx.x] : 0;
    sh[threadIdx.x] = v;
    __syncthreads();
    #pragma unroll
    for (int off = 1; off < MAX_SCAN_BLOCKS; off <<= 1) {
        int t = (threadIdx.x >= off) ? sh[threadIdx.x - off] : 0;
        __syncthreads();
        sh[threadIdx.x] += t;
        __syncthreads();
    }
    g_bsum[threadIdx.x] = sh[threadIdx.x] - v;
}
__global__ void k_scan_add(int n, int E) {
    int i = blockIdx.x * SCAN_BS + threadIdx.x;
    if (i < n) {
        int excl = g_incl[i] - g_cnt[i] + g_bsum[blockIdx.x];
        g_rowstart[i] = excl;
        if (i == n - 1) g_rowstart[n] = excl + g_cnt[i];
    }
}
__global__ void k_fill(const int* __restrict__ edge, int E) {
    int i = blockIdx.x * blockDim.x + threadIdx.x;
    if (i < E) {
        int s = edge_src(edge, E, i);
        int d = edge_dst(edge, E, i);
        int pos = g_rowstart[d] + atomicAdd(&g_cursor[d], 1);
        g_csr[pos] = make_int2(s, __float_as_int(g_dis[s] * g_dis[d]));
    }
}

// ---------------- bf16 / mma helpers ----------------------------------------
__device__ __forceinline__ u32 pack_bf2(float x, float y) {
    u32 lo = (u32)__bfloat16_as_ushort(__float2bfloat16_rn(x));
    u32 hi = (u32)__bfloat16_as_ushort(__float2bfloat16_rn(y));
    return lo | (hi << 16);
}
__device__ __forceinline__ void mma16816(float* c, const u32* a, const u32* b) {
    asm volatile(
        "mma.sync.aligned.m16n8k16.row.col.f32.bf16.bf16.f32 "
        "{%0,%1,%2,%3},{%4,%5,%6,%7},{%8,%9},{%0,%1,%2,%3};"
        : "+f"(c[0]), "+f"(c[1]), "+f"(c[2]), "+f"(c[3])
        : "r"(a[0]), "r"(a[1]), "r"(a[2]), "r"(a[3]), "r"(b[0]), "r"(b[1]));
}
#define LDSM4(r0, r1, r2, r3, addr) \
    asm volatile("ldmatrix.sync.aligned.m8n8.x4.shared.b16 {%0,%1,%2,%3}, [%4];" \
                 : "=r"(r0), "=r"(r1), "=r"(r2), "=r"(r3) : "r"(addr))
__device__ __forceinline__ u32 smem_u32(const void* p) {
    return (u32)__cvta_generic_to_shared(p);
}

// ---------------- W prep: fp32 row-major -> transposed bf16 hi/lo images ----
__global__ void k_wprep(const float* __restrict__ Wa, const float* __restrict__ Wb,
                        const float* __restrict__ Wc, const float* __restrict__ Wd)
{
    const float* Ws4[4] = {Wa, Wb, Wc, Wd};
    const float* W = Ws4[blockIdx.x];
    __nv_bfloat16* imgh = g_wimg[2 * blockIdx.x];
    __nv_bfloat16* imgl = g_wimg[2 * blockIdx.x + 1];
    int tid = threadIdx.x;
    #pragma unroll
    for (int i = 0; i < 16; i++) {
        int idx = tid + i * 256;
        int k   = idx >> 5;
        int n0  = (idx & 31) * 4;
        float4 w = ((const float4*)(W + (size_t)k * D))[idx & 31];
        float ws[4] = {w.x, w.y, w.z, w.w};
        #pragma unroll
        for (int j = 0; j < 4; j++) {
            float hi = __bfloat162float(__float2bfloat16_rn(ws[j]));
            imgh[(n0 + j) * WST + k] = __float2bfloat16_rn(hi);
            imgl[(n0 + j) * WST + k] = __float2bfloat16_rn(ws[j] - hi);
        }
    }
}

// ---------------- persistent tensor-core GEMM (bf16 3-term split) -----------
// out = f(A @ W + bias). Grid = GEMM_GRID persistent CTAs; each loads W ONCE
// then grid-strides over 64-row tiles: fill A -> sync -> mma+epi -> sync.
__global__ void __launch_bounds__(256, 2)
k_gemm_tc(const float* __restrict__ A, int n, int wsel,
          const float* __restrict__ bias, int relu, float* __restrict__ out,
          const int* __restrict__ edge, int E, int hist)
{
    extern __shared__ __align__(16) __nv_bfloat16 sm[];
    __nv_bfloat16* Ah = sm;
    __nv_bfloat16* Al = sm + AL_OFF;
    __nv_bfloat16* Wh = sm + WH_OFF;

    const int tid = threadIdx.x;

    // folded degree histogram (fire-and-forget REDs; conv1 only)
    if (hist) {
        int per  = (E + gridDim.x - 1) / gridDim.x;
        int base = blockIdx.x * per;
        int lim  = base + per; if (lim > E) lim = E;
        for (int i = base + tid; i < lim; i += 256)
            atomicAdd(&g_cnt[edge_dst(edge, E, i)], 1);
    }

    // ---- copy W hi/lo image ONCE (68KB from L2) -----------------------------
    {
        const float4* src = (const float4*)g_wimg[2 * wsel];
        float4* dst = (float4*)Wh;
        #pragma unroll
        for (int i = 0; i < 17; i++)
            dst[tid + i * 256] = src[tid + i * 256];
    }

    const int wid  = tid >> 5, lane = tid & 31;
    const int wm = wid >> 2;
    const int wn = wid & 3;
    const int g  = lane >> 2, t = lane & 3;

    const u32 smbase = smem_u32(sm);
    const int lr = lane & 15;
    const int kh = (lane >> 4) * 8;
    const u32 aH0 = smbase + ((wm * 32 + lr) * AST + kh) * 2;
    const u32 aH1 = aH0 + 16 * AST * 2;
    const u32 aL0 = aH0 + AL_OFF * 2;
    const u32 aL1 = aH1 + AL_OFF * 2;
    const int bl8 = lane & 7;
    const int sel = lane >> 3;
    const int nse = (sel >> 1) * 8;
    const int kse = (sel & 1) * 8;
    const u32 bH0 = smbase + WH_OFF * 2 +
                    ((wn * 32 + nse + bl8) * WST + kse) * 2;
    const u32 bH1 = bH0 + 16 * WST * 2;
    const u32 bL0 = bH0 + 128 * WST * 2;
    const u32 bL1 = bH1 + 128 * WST * 2;

    const int nblocks = (n + GT - 1) / GT;
    for (int rb = blockIdx.x; rb < nblocks; rb += gridDim.x) {
        const int rowBlock = rb * GT;

        // ---- fill A hi/lo, zero OOB rows ------------------------------------
        #pragma unroll
        for (int i = 0; i < 8; i++) {
            int idx = tid + i * 256;
            int r   = idx >> 5;
            int c4  = idx & 31;
            int grow = rowBlock + r;
            float4 v = make_float4(0.f, 0.f, 0.f, 0.f);
            if (grow < n) v = ((const float4*)(A + (size_t)grow * D))[c4];
            float hx = __bfloat162float(__float2bfloat16_rn(v.x));
            float hy = __bfloat162float(__float2bfloat16_rn(v.y));
            float hz = __bfloat162float(__float2bfloat16_rn(v.z));
            float hw = __bfloat162float(__float2bfloat16_rn(v.w));
            u32* ph = (u32*)(Ah + r * AST + c4 * 4);
            u32* pl = (u32*)(Al + r * AST + c4 * 4);
            ph[0] = pack_bf2(hx, hy);             ph[1] = pack_bf2(hz, hw);
            pl[0] = pack_bf2(v.x - hx, v.y - hy); pl[1] = pack_bf2(v.z - hz, v.w - hw);
        }
        __syncthreads();

        float acc[2][4][4];
        #pragma unroll
        for (int mf = 0; mf < 2; mf++)
            #pragma unroll
            for (int nf = 0; nf < 4; nf++)
                #pragma unroll
                for (int c = 0; c < 4; c++) acc[mf][nf][c] = 0.f;

        #pragma unroll
        for (int ks = 0; ks < 8; ks++) {
            const u32 kb = ks * 32;
            u32 ah[2][4], al[2][4], bh[8], blo[8];
            LDSM4(ah[0][0], ah[0][1], ah[0][2], ah[0][3], aH0 + kb);
            LDSM4(ah[1][0], ah[1][1], ah[1][2], ah[1][3], aH1 + kb);
            LDSM4(bh[0], bh[1], bh[2], bh[3], bH0 + kb);
            LDSM4(bh[4], bh[5], bh[6], bh[7], bH1 + kb);
            LDSM4(al[0][0], al[0][1], al[0][2], al[0][3], aL0 + kb);
            LDSM4(al[1][0], al[1][1], al[1][2], al[1][3], aL1 + kb);
            LDSM4(blo[0], blo[1], blo[2], blo[3], bL0 + kb);
            LDSM4(blo[4], blo[5], blo[6], blo[7], bL1 + kb);
            #pragma unroll
            for (int mf = 0; mf < 2; mf++)
                #pragma unroll
                for (int nf = 0; nf < 4; nf++)
                    mma16816(acc[mf][nf], ah[mf], bh + 2 * nf);
            #pragma unroll
            for (int mf = 0; mf < 2; mf++)
                #pragma unroll
                for (int nf = 0; nf < 4; nf++)
                    mma16816(acc[mf][nf], al[mf], bh + 2 * nf);
            #pragma unroll
            for (int mf = 0; mf < 2; mf++)
                #pragma unroll
                for (int nf = 0; nf < 4; nf++)
                    mma16816(acc[mf][nf], ah[mf], blo + 2 * nf);
        }

        // ---- epilogue ---------------------------------------------------------
        #pragma unroll
        for (int mf = 0; mf < 2; mf++) {
            #pragma unroll
            for (int nf = 0; nf < 4; nf++) {
                int row = rowBlock + wm * 32 + mf * 16 + g;
                int col = wn * 32 + nf * 8 + 2 * t;
                float b0 = 0.f, b1 = 0.f;
                if (bias) { b0 = bias[col]; b1 = bias[col + 1]; }
                float2 v0, v1;
                v0.x = acc[mf][nf][0] + b0; v0.y = acc[mf][nf][1] + b1;
                v1.x = acc[mf][nf][2] + b0; v1.y = acc[mf][nf][3] + b1;
                if (relu) {
                    v0.x = fmaxf(v0.x, 0.f); v0.y = fmaxf(v0.y, 0.f);
                    v1.x = fmaxf(v1.x, 0.f); v1.y = fmaxf(v1.y, 0.f);
                }
                if (row < n)     *(float2*)(out + (size_t)row * D + col)       = v0;
                if (row + 8 < n) *(float2*)(out + (size_t)(row + 8) * D + col) = v1;
            }
        }
        __syncthreads();   // before next tile's A fill overwrites Ah/Al
    }
}

// ---------------- CSR gather aggregation -----------------------------------
__global__ void k_gather(const float* __restrict__ xw,
                         float* __restrict__ out,
                         const float* __restrict__ bias, int relu,
                         int n)
{
    int warp = (blockIdx.x * blockDim.x + threadIdx.x) >> 5;
    int lane = threadIdx.x & 31;
    if (warp >= n) return;
    const int d = warp;

    float dis = g_dis[d];
    float dis2 = dis * dis;
    float4 self = ((const float4*)(xw + (size_t)d * D))[lane];
    float4 acc;
    acc.x = self.x * dis2; acc.y = self.y * dis2;
    acc.z = self.z * dis2; acc.w = self.w * dis2;

    int e   = g_rowstart[d];
    int end = g_rowstart[d + 1];

    for (; e + 1 < end; e += 2) {
        int2 e0 = g_csr[e];
        int2 e1 = g_csr[e + 1];
        float c0 = __int_as_float(e0.y);
        float c1 = __int_as_float(e1.y);
        float4 v0 = ((const float4*)(xw + (size_t)e0.x * D))[lane];
        float4 v1 = ((const float4*)(xw + (size_t)e1.x * D))[lane];
        acc.x = fmaf(c0, v0.x, acc.x); acc.y = fmaf(c0, v0.y, acc.y);
        acc.z = fmaf(c0, v0.z, acc.z); acc.w = fmaf(c0, v0.w, acc.w);
        acc.x = fmaf(c1, v1.x, acc.x); acc.y = fmaf(c1, v1.y, acc.y);
        acc.z = fmaf(c1, v1.z, acc.z); acc.w = fmaf(c1, v1.w, acc.w);
    }
    if (e < end) {
        int2 e0 = g_csr[e];
        float c0 = __int_as_float(e0.y);
        float4 v0 = ((const float4*)(xw + (size_t)e0.x * D))[lane];
        acc.x = fmaf(c0, v0.x, acc.x); acc.y = fmaf(c0, v0.y, acc.y);
        acc.z = fmaf(c0, v0.z, acc.z); acc.w = fmaf(c0, v0.w, acc.w);
    }

    const int col = lane * 4;
    acc.x += bias[col]; acc.y += bias[col + 1];
    acc.z += bias[col + 2]; acc.w += bias[col + 3];
    if (relu) {
        acc.x = fmaxf(acc.x, 0.f); acc.y = fmaxf(acc.y, 0.f);
        acc.z = fmaxf(acc.z, 0.f); acc.w = fmaxf(acc.w, 0.f);
    }
    ((float4*)(out + (size_t)d * D))[lane] = acc;
}

// ---------------- launch ---------------------------------------------------
extern "C" void kernel_launch(void* const* d_in, const int* in_sizes, int n_in,
                              void* d_out, int out_size)
{
    const float* x    = (const float*)d_in[0];
    const int*   edge = (const int*)d_in[1];   // int32 or int64 (detected)
    const float* W1 = (const float*)d_in[2]; const float* b1 = (const float*)d_in[3];
    const float* W2 = (const float*)d_in[4]; const float* b2 = (const float*)d_in[5];
    const float* Wv = (const float*)d_in[6]; const float* bv = (const float*)d_in[7];
    const float* Wt = (const float*)d_in[8]; const float* bt = (const float*)d_in[9];

    const int n = in_sizes[0] / D;
    const int E = in_sizes[1] / 2;

    float* out_h = (float*)d_out;
    float* out_v = out_h + (size_t)n * D;
    float* out_t = out_v + (size_t)n * D;

    float* xw = nullptr; cudaGetSymbolAddress((void**)&xw, g_xw);
    float* h  = nullptr; cudaGetSymbolAddress((void**)&h,  g_h);

    cudaFuncSetAttribute(k_gemm_tc, cudaFuncAttributeMaxDynamicSharedMemorySize, SMEM_TC);

    const int TB = 256;
    const int nscan = (n + SCAN_BS - 1) / SCAN_BS;
    const int gatherGrid = (n + 7) / 8;

    // launches 1-3 small so the conv1 GEMM is the 4th (ncu sample slot)
    k_detect<<<1, 512>>>(edge, 2 * E);
    k_zero<<<(n + TB - 1) / TB, TB>>>(n);
    k_wprep<<<4, 256>>>(W1, W2, Wv, Wt);
    // 4: conv1 GEMM (persistent; + folded degree histogram)
    k_gemm_tc<<<GEMM_GRID, TB, SMEM_TC>>>(x, n, 0, nullptr, 0, xw, edge, E, 1);
    // normalization + CSR
    k_scan_block<<<nscan, SCAN_BS>>>(n);
    k_scan_tops<<<1, MAX_SCAN_BLOCKS>>>(nscan);
    k_scan_add<<<nscan, SCAN_BS>>>(n, E);
    k_fill<<<(E + TB - 1) / TB, TB>>>(edge, E);
    // conv1 aggregate -> h
    k_gather<<<gatherGrid, TB>>>(xw, h, b1, 1, n);
    // conv2
    k_gemm_tc<<<GEMM_GRID, TB, SMEM_TC>>>(h, n, 1, nullptr, 0, xw,
                                          nullptr, 0, 0);
    k_gather<<<gatherGrid, TB>>>(xw, out_h, b2, 0, n);
    // heads
    k_gemm_tc<<<GEMM_GRID, TB, SMEM_TC>>>(out_h, n, 2, bv, 1, out_v,
                                          nullptr, 0, 0);
    k_gemm_tc<<<GEMM_GRID, TB, SMEM_TC>>>(out_h, n, 3, bt, 1, out_t,
                                          nullptr, 0, 0);
}